// round 2
// baseline (speedup 1.0000x reference)
#include <cuda_runtime.h>
#include <math.h>

// Problem constants (fixed by the reference)
constexpr int NQ   = 8192;   // query rows
constexpr int MKV  = 8192;   // context rows
constexpr int DIMC = 1024;   // feature dim

// Scratch: __device__ globals (allocation-free rule)
__device__ float g_q[(size_t)NQ  * DIMC];
__device__ float g_k[(size_t)MKV * DIMC];
__device__ float g_v[(size_t)MKV * DIMC];
__device__ float g_s[(size_t)NQ  * MKV];   // 256 MB score/prob matrix

// ---------------------------------------------------------------------------
// 128x128x8 SIMT SGEMM, 256 threads, 8x8 microtile, double-buffered.
// C[M,N] = alpha * A[M,K] @ op(B) (+ bias[N])
//   TRANS_B = false : B is [K,N] row-major
//   TRANS_B = true  : B is [N,K] row-major (i.e. C = A @ B^T)
// All dims must be multiples of 128 (M,N) and 8 (K) — true for this problem.
// ---------------------------------------------------------------------------
template<bool TRANS_B, bool ADD_BIAS>
__global__ __launch_bounds__(256, 2)
void sgemm128(const float* __restrict__ A, const float* __restrict__ B,
              const float* __restrict__ bias, float* __restrict__ C,
              int Nd, int Kd, float alpha)
{
    __shared__ float As[2][8][128];
    __shared__ float Bs[2][8][128];

    const int tid = threadIdx.x;
    const int tx  = tid & 15;      // 0..15 -> 8 cols each
    const int ty  = tid >> 4;      // 0..15 -> 8 rows each
    const int m0  = blockIdx.y * 128;
    const int n0  = blockIdx.x * 128;

    // A tile loader: 128 rows x 8 k-cols, one float4 per thread
    const int aRow = tid >> 1;           // 0..127
    const int aCol = (tid & 1) << 2;     // 0 or 4
    const float* Ag = A + (size_t)(m0 + aRow) * Kd + aCol;

    // B tile loader
    int bRow, bCol;
    const float* Bg;
    size_t bStep;                         // pointer advance per k-tile
    if (TRANS_B) {
        bRow = tid >> 1;                 // n index 0..127
        bCol = (tid & 1) << 2;           // k index 0 or 4
        Bg = B + (size_t)(n0 + bRow) * Kd + bCol;
        bStep = 8;
    } else {
        bRow = tid >> 5;                 // k index 0..7
        bCol = (tid & 31) << 2;          // n index 0..124
        Bg = B + (size_t)bRow * Nd + (n0 + bCol);
        bStep = (size_t)8 * Nd;
    }

    const int nT = Kd >> 3;

    // ---- load tile 0 ----
    {
        float4 va = *(const float4*)Ag;
        As[0][aCol + 0][aRow] = va.x;
        As[0][aCol + 1][aRow] = va.y;
        As[0][aCol + 2][aRow] = va.z;
        As[0][aCol + 3][aRow] = va.w;
        float4 vb = *(const float4*)Bg;
        if (TRANS_B) {
            Bs[0][bCol + 0][bRow] = vb.x;
            Bs[0][bCol + 1][bRow] = vb.y;
            Bs[0][bCol + 2][bRow] = vb.z;
            Bs[0][bCol + 3][bRow] = vb.w;
        } else {
            *(float4*)&Bs[0][bRow][bCol] = vb;
        }
    }
    Ag += 8;
    Bg += bStep;
    __syncthreads();

    float acc[8][8];
    #pragma unroll
    for (int i = 0; i < 8; i++)
        #pragma unroll
        for (int j = 0; j < 8; j++)
            acc[i][j] = 0.0f;

    for (int kt = 0; kt < nT; kt++) {
        const int  cur = kt & 1;
        const bool pf  = (kt + 1 < nT);
        float4 va, vb;
        if (pf) {
            va = *(const float4*)Ag;
            vb = *(const float4*)Bg;
            Ag += 8;
            Bg += bStep;
        }

        #pragma unroll
        for (int kk = 0; kk < 8; kk++) {
            float ar[8], br[8];
            *(float4*)&ar[0] = *(const float4*)&As[cur][kk][ty * 8];
            *(float4*)&ar[4] = *(const float4*)&As[cur][kk][ty * 8 + 4];
            *(float4*)&br[0] = *(const float4*)&Bs[cur][kk][tx * 8];
            *(float4*)&br[4] = *(const float4*)&Bs[cur][kk][tx * 8 + 4];
            #pragma unroll
            for (int i = 0; i < 8; i++)
                #pragma unroll
                for (int j = 0; j < 8; j++)
                    acc[i][j] = fmaf(ar[i], br[j], acc[i][j]);
        }

        if (pf) {
            const int nxt = cur ^ 1;
            As[nxt][aCol + 0][aRow] = va.x;
            As[nxt][aCol + 1][aRow] = va.y;
            As[nxt][aCol + 2][aRow] = va.z;
            As[nxt][aCol + 3][aRow] = va.w;
            if (TRANS_B) {
                Bs[nxt][bCol + 0][bRow] = vb.x;
                Bs[nxt][bCol + 1][bRow] = vb.y;
                Bs[nxt][bCol + 2][bRow] = vb.z;
                Bs[nxt][bCol + 3][bRow] = vb.w;
            } else {
                *(float4*)&Bs[nxt][bRow][bCol] = vb;
            }
        }
        __syncthreads();
    }

    // ---- epilogue ----
    float bvc[8];
    if (ADD_BIAS) {
        #pragma unroll
        for (int j = 0; j < 8; j++) bvc[j] = bias[n0 + tx * 8 + j];
    }
    #pragma unroll
    for (int i = 0; i < 8; i++) {
        float* Cp = C + (size_t)(m0 + ty * 8 + i) * Nd + n0 + tx * 8;
        float4 o0, o1;
        o0.x = acc[i][0] * alpha; o0.y = acc[i][1] * alpha;
        o0.z = acc[i][2] * alpha; o0.w = acc[i][3] * alpha;
        o1.x = acc[i][4] * alpha; o1.y = acc[i][5] * alpha;
        o1.z = acc[i][6] * alpha; o1.w = acc[i][7] * alpha;
        if (ADD_BIAS) {
            o0.x += bvc[0]; o0.y += bvc[1]; o0.z += bvc[2]; o0.w += bvc[3];
            o1.x += bvc[4]; o1.y += bvc[5]; o1.z += bvc[6]; o1.w += bvc[7];
        }
        *(float4*)Cp       = o0;
        *(float4*)(Cp + 4) = o1;
    }
}

// ---------------------------------------------------------------------------
// Row softmax over S[NQ, MKV], in place. One CTA per row, values live in
// registers between passes: one global read + one global write per element.
// ---------------------------------------------------------------------------
__global__ __launch_bounds__(256)
void softmax_rows(float* __restrict__ S)
{
    const int row  = blockIdx.x;
    const int tid  = threadIdx.x;
    const int lane = tid & 31;
    const int wrp  = tid >> 5;
    float4* p4 = (float4*)(S + (size_t)row * MKV);   // 2048 float4 per row

    float4 v[8];
    float m = -3.0e38f;
    #pragma unroll
    for (int i = 0; i < 8; i++) {
        v[i] = p4[tid + i * 256];
        m = fmaxf(m, fmaxf(fmaxf(v[i].x, v[i].y), fmaxf(v[i].z, v[i].w)));
    }

    __shared__ float red[8];
    // warp-level max
    #pragma unroll
    for (int s = 16; s > 0; s >>= 1)
        m = fmaxf(m, __shfl_xor_sync(0xffffffffu, m, s));
    if (lane == 0) red[wrp] = m;
    __syncthreads();
    m = red[lane & 7];
    #pragma unroll
    for (int s = 4; s > 0; s >>= 1)
        m = fmaxf(m, __shfl_xor_sync(0xffffffffu, m, s));
    m = __shfl_sync(0xffffffffu, m, 0);

    float sum = 0.0f;
    #pragma unroll
    for (int i = 0; i < 8; i++) {
        v[i].x = __expf(v[i].x - m);
        v[i].y = __expf(v[i].y - m);
        v[i].z = __expf(v[i].z - m);
        v[i].w = __expf(v[i].w - m);
        sum += (v[i].x + v[i].y) + (v[i].z + v[i].w);
    }

    // warp-level sum
    #pragma unroll
    for (int s = 16; s > 0; s >>= 1)
        sum += __shfl_xor_sync(0xffffffffu, sum, s);
    __syncthreads();          // red[] reuse
    if (lane == 0) red[wrp] = sum;
    __syncthreads();
    sum = red[lane & 7];
    #pragma unroll
    for (int s = 4; s > 0; s >>= 1)
        sum += __shfl_xor_sync(0xffffffffu, sum, s);
    sum = __shfl_sync(0xffffffffu, sum, 0);

    const float inv = 1.0f / sum;
    #pragma unroll
    for (int i = 0; i < 8; i++) {
        v[i].x *= inv; v[i].y *= inv; v[i].z *= inv; v[i].w *= inv;
        p4[tid + i * 256] = v[i];
    }
}

// ---------------------------------------------------------------------------
extern "C" void kernel_launch(void* const* d_in, const int* in_sizes, int n_in,
                              void* d_out, int out_size)
{
    const float* x   = (const float*)d_in[0];
    const float* ctx = (const float*)d_in[1];
    const float* Wq  = (const float*)d_in[2];
    const float* bq  = (const float*)d_in[3];
    const float* Wk  = (const float*)d_in[4];
    const float* bk  = (const float*)d_in[5];
    const float* Wv  = (const float*)d_in[6];
    const float* bv  = (const float*)d_in[7];
    float* out = (float*)d_out;

    float *qp, *kp, *vp, *sp;
    cudaGetSymbolAddress((void**)&qp, g_q);
    cudaGetSymbolAddress((void**)&kp, g_k);
    cudaGetSymbolAddress((void**)&vp, g_v);
    cudaGetSymbolAddress((void**)&sp, g_s);

    const dim3 blk(256);
    const float scale = 1.0f / 32.0f;   // 1/sqrt(1024)

    // Projections: q = x@Wq + bq ; k = ctx@Wk + bk ; v = ctx@Wv + bv
    sgemm128<false, true><<<dim3(DIMC / 128, NQ  / 128), blk>>>(x,   Wq, bq, qp, DIMC, DIMC, 1.0f);
    sgemm128<false, true><<<dim3(DIMC / 128, MKV / 128), blk>>>(ctx, Wk, bk, kp, DIMC, DIMC, 1.0f);
    sgemm128<false, true><<<dim3(DIMC / 128, MKV / 128), blk>>>(ctx, Wv, bv, vp, DIMC, DIMC, 1.0f);

    // Scores: S = (q @ k^T) * scale
    sgemm128<true, false><<<dim3(MKV / 128, NQ / 128), blk>>>(qp, kp, nullptr, sp, MKV, DIMC, scale);

    // Softmax rows of S (in place)
    softmax_rows<<<NQ, 256>>>(sp);

    // Output: O = P @ v
    sgemm128<false, false><<<dim3(DIMC / 128, NQ / 128), blk>>>(sp, vp, nullptr, out, DIMC, MKV, 1.0f);
}

// round 3
// speedup vs baseline: 2.9790x; 2.9790x over previous
#include <cuda_runtime.h>
#include <cuda_bf16.h>
#include <stdint.h>
#include <math.h>

constexpr int NQ   = 8192;
constexpr int MKV  = 8192;
constexpr int DIMC = 1024;

// ---------------- scratch (__device__ globals; allocation-free rule) --------
__device__ __nv_bfloat16 g_xh[(size_t)NQ*DIMC],  g_xl[(size_t)NQ*DIMC];
__device__ __nv_bfloat16 g_ch[(size_t)MKV*DIMC], g_cl[(size_t)MKV*DIMC];
__device__ __nv_bfloat16 g_wqh[(size_t)DIMC*DIMC], g_wql[(size_t)DIMC*DIMC];
__device__ __nv_bfloat16 g_wkh[(size_t)DIMC*DIMC], g_wkl[(size_t)DIMC*DIMC];
__device__ __nv_bfloat16 g_wvh[(size_t)DIMC*DIMC], g_wvl[(size_t)DIMC*DIMC];
__device__ __nv_bfloat16 g_qh[(size_t)NQ*DIMC],  g_ql[(size_t)NQ*DIMC];
__device__ __nv_bfloat16 g_kh[(size_t)MKV*DIMC], g_kl[(size_t)MKV*DIMC];
__device__ __nv_bfloat16 g_vh[(size_t)MKV*DIMC], g_vl[(size_t)MKV*DIMC];
__device__ float         g_s [(size_t)NQ*MKV];
__device__ __nv_bfloat16 g_ph[(size_t)NQ*MKV],  g_pl[(size_t)NQ*MKV];

// ---------------- PTX helpers ----------------------------------------------
__device__ __forceinline__ uint32_t s2u(const void* p) {
    uint32_t a;
    asm("{ .reg .u64 t; cvta.to.shared.u64 t, %1; cvt.u32.u64 %0, t; }"
        : "=r"(a) : "l"(p));
    return a;
}
#define CPASYNC16(sa, gp) \
    asm volatile("cp.async.cg.shared.global [%0], [%1], 16;" :: "r"(sa), "l"(gp))
#define CPCOMMIT() asm volatile("cp.async.commit_group;")
#define CPWAIT(n)  asm volatile("cp.async.wait_group %0;" :: "n"(n))

#define LDSM_X4(r0,r1,r2,r3,a) \
    asm volatile("ldmatrix.sync.aligned.m8n8.x4.shared.b16 {%0,%1,%2,%3}, [%4];" \
        : "=r"(r0),"=r"(r1),"=r"(r2),"=r"(r3) : "r"(a))
#define LDSM_X4_T(r0,r1,r2,r3,a) \
    asm volatile("ldmatrix.sync.aligned.m8n8.x4.trans.shared.b16 {%0,%1,%2,%3}, [%4];" \
        : "=r"(r0),"=r"(r1),"=r"(r2),"=r"(r3) : "r"(a))

#define MMA16816(c0,c1,c2,c3,a0,a1,a2,a3,b0,b1) \
    asm volatile("mma.sync.aligned.m16n8k16.row.col.f32.bf16.bf16.f32 " \
        "{%0,%1,%2,%3}, {%4,%5,%6,%7}, {%8,%9}, {%0,%1,%2,%3};" \
        : "+f"(c0),"+f"(c1),"+f"(c2),"+f"(c3) \
        : "r"(a0),"r"(a1),"r"(a2),"r"(a3), "r"(b0),"r"(b1))

__device__ __forceinline__ void split2(float a, float b,
                                       __nv_bfloat162& h, __nv_bfloat162& l) {
    __nv_bfloat16 ha = __float2bfloat16(a);
    __nv_bfloat16 hb = __float2bfloat16(b);
    h.x = ha; h.y = hb;
    l.x = __float2bfloat16(a - __bfloat162float(ha));
    l.y = __float2bfloat16(b - __bfloat162float(hb));
}

// ---------------- input split kernel (fp32 -> hi/lo bf16) -------------------
__global__ __launch_bounds__(256)
void splitk(const float* __restrict__ in, __nv_bfloat16* __restrict__ hi,
            __nv_bfloat16* __restrict__ lo, int n4)
{
    int i = blockIdx.x * 256 + threadIdx.x;
    if (i >= n4) return;
    float4 v = ((const float4*)in)[i];
    __nv_bfloat162 h0, l0, h1, l1;
    split2(v.x, v.y, h0, l0);
    split2(v.z, v.w, h1, l1);
    ((__nv_bfloat162*)hi)[2*i]   = h0;
    ((__nv_bfloat162*)hi)[2*i+1] = h1;
    ((__nv_bfloat162*)lo)[2*i]   = l0;
    ((__nv_bfloat162*)lo)[2*i+1] = l1;
}

// ---------------- split-bf16 GEMM (3-pass hi/lo) ---------------------------
// C[M,N] = sum over passes of Ap @ op(Bp):
//   pass0: A_hi * B_hi, pass1: A_lo * B_hi, pass2: A_hi * B_lo
// A: [M,K] row-major bf16.  TRANS_B ? B:[N,K] : B:[K,N] row-major bf16.
// PROJ epilogue: out_{hi,lo} = split((acc + bias[n]) * alpha)
// else:          Cf[m][n] = acc (fp32)
constexpr int BM = 128, BN = 128, BK = 64;

template<bool TRANS_B, bool PROJ>
__global__ __launch_bounds__(256, 2)
void bgemm(const __nv_bfloat16* __restrict__ Ahi, const __nv_bfloat16* __restrict__ Alo,
           const __nv_bfloat16* __restrict__ Bhi, const __nv_bfloat16* __restrict__ Blo,
           int lda, int ldb, int K,
           const float* __restrict__ bias, float alpha,
           float* __restrict__ Cf,
           __nv_bfloat16* __restrict__ Chi, __nv_bfloat16* __restrict__ Clo,
           int ldc)
{
    extern __shared__ char smem[];
    const uint32_t sA = s2u(smem);            // 2 stages x 16KB
    const uint32_t sB = sA + 32768;           // 2 stages x 16KB

    const int tid  = threadIdx.x;
    const int lane = tid & 31;
    const int wid  = tid >> 5;
    const int wm0  = (wid >> 2) * 64;         // warp m offset in CTA tile
    const int wn0  = (wid & 3) * 32;          // warp n offset
    const int m0   = blockIdx.y * BM;
    const int n0   = blockIdx.x * BN;

    // ---- global->smem loader geometry ----
    // A tile: 128 rows x 64 cols bf16 = rows of 128B = 8 chunks of 16B
    const int aRow0  = tid >> 3;              // +32*i
    const int aChunk = tid & 7;
    const uint32_t aSoff = (uint32_t)aRow0 * 128 + ((aChunk ^ (aRow0 & 7)) << 4);
    // B tile, NN: 64 rows x 128 cols = rows of 256B = 16 chunks
    const int bRow0  = TRANS_B ? (tid >> 3) : (tid >> 4);
    const int bChunk = TRANS_B ? (tid & 7)  : (tid & 15);
    const uint32_t bSoff = TRANS_B
        ? ((uint32_t)bRow0 * 128 + ((bChunk ^ (bRow0 & 7)) << 4))
        : ((uint32_t)bRow0 * 256 + ((bChunk ^ (bRow0 & 7)) << 4));

    const __nv_bfloat16* APs[3] = { Ahi, Alo, Ahi };
    const __nv_bfloat16* BPs[3] = { Bhi, Bhi, Blo };

    auto loadA = [&](int stage, int k0, const __nv_bfloat16* Ap) {
        uint32_t s = sA + (uint32_t)stage * 16384 + aSoff;
        const __nv_bfloat16* g = Ap + (size_t)(m0 + aRow0) * lda + k0 + aChunk * 8;
        #pragma unroll
        for (int i = 0; i < 4; i++)
            CPASYNC16(s + i * 4096, g + (size_t)32 * i * lda);
    };
    auto loadB = [&](int stage, int k0, const __nv_bfloat16* Bp) {
        uint32_t s = sB + (uint32_t)stage * 16384 + bSoff;
        if (TRANS_B) {
            const __nv_bfloat16* g = Bp + (size_t)(n0 + bRow0) * ldb + k0 + bChunk * 8;
            #pragma unroll
            for (int i = 0; i < 4; i++)
                CPASYNC16(s + i * 4096, g + (size_t)32 * i * ldb);
        } else {
            const __nv_bfloat16* g = Bp + (size_t)(k0 + bRow0) * ldb + n0 + bChunk * 8;
            #pragma unroll
            for (int i = 0; i < 4; i++)
                CPASYNC16(s + i * 4096, g + (size_t)16 * i * ldb);
        }
    };

    // ---- mma fragment geometry ----
    const int sub  = lane >> 3;               // which 8x8 matrix in ldmatrix.x4
    const int roct = lane & 7;

    int arow[4];                               // smem row for A ldmatrix, per m-tile
    #pragma unroll
    for (int mt = 0; mt < 4; mt++)
        arow[mt] = wm0 + mt * 16 + (sub & 1) * 8 + roct;

    int nrow[2];                               // NT: smem row per n-pair
    uint32_t bnnBase[2];                       // NN: precomputed addr component
    #pragma unroll
    for (int np = 0; np < 2; np++) {
        nrow[np] = wn0 + np * 16 + (sub >> 1) * 8 + roct;
        int nch  = (wn0 >> 3) + np * 2 + (sub >> 1);
        bnnBase[np] = (uint32_t)(((sub & 1) * 8 + roct) * 256) + ((nch ^ roct) << 4);
    }

    float acc[4][4][4];
    #pragma unroll
    for (int mt = 0; mt < 4; mt++)
        #pragma unroll
        for (int nt = 0; nt < 4; nt++)
            #pragma unroll
            for (int e = 0; e < 4; e++)
                acc[mt][nt][e] = 0.0f;

    const int nkt   = K >> 6;                  // k-tiles per pass
    const int total = nkt * 3;

    loadA(0, 0, APs[0]);
    loadB(0, 0, BPs[0]);
    CPCOMMIT();

    int pfP = 0, pfK = 0;                      // last prefetched (pass, ktile)
    for (int it = 0; it < total; ++it) {
        if (it + 1 < total) {
            int p = pfP, k = pfK + 1;
            if (k == nkt) { k = 0; ++p; }
            loadA((it + 1) & 1, k * BK, APs[p]);
            loadB((it + 1) & 1, k * BK, BPs[p]);
            CPCOMMIT();
            pfP = p; pfK = k;
            CPWAIT(1);
        } else {
            CPWAIT(0);
        }
        __syncthreads();

        const uint32_t aBase = sA + (uint32_t)(it & 1) * 16384;
        const uint32_t bBase = sB + (uint32_t)(it & 1) * 16384;

        #pragma unroll
        for (int kk = 0; kk < 4; kk++) {
            uint32_t af[4][4];
            #pragma unroll
            for (int mt = 0; mt < 4; mt++) {
                int kch = kk * 2 + (sub >> 1);
                uint32_t ad = aBase + (uint32_t)arow[mt] * 128 + ((kch ^ (arow[mt] & 7)) << 4);
                LDSM_X4(af[mt][0], af[mt][1], af[mt][2], af[mt][3], ad);
            }
            uint32_t bf[2][4];
            #pragma unroll
            for (int np = 0; np < 2; np++) {
                if (TRANS_B) {
                    int kch = kk * 2 + (sub & 1);
                    uint32_t bd = bBase + (uint32_t)nrow[np] * 128 + ((kch ^ (nrow[np] & 7)) << 4);
                    LDSM_X4(bf[np][0], bf[np][1], bf[np][2], bf[np][3], bd);
                } else {
                    uint32_t bd = bBase + (uint32_t)kk * 4096 + bnnBase[np];
                    LDSM_X4_T(bf[np][0], bf[np][1], bf[np][2], bf[np][3], bd);
                }
            }
            #pragma unroll
            for (int mt = 0; mt < 4; mt++) {
                #pragma unroll
                for (int nt = 0; nt < 4; nt++) {
                    uint32_t b0 = bf[nt >> 1][(nt & 1) * 2];
                    uint32_t b1 = bf[nt >> 1][(nt & 1) * 2 + 1];
                    MMA16816(acc[mt][nt][0], acc[mt][nt][1], acc[mt][nt][2], acc[mt][nt][3],
                             af[mt][0], af[mt][1], af[mt][2], af[mt][3], b0, b1);
                }
            }
        }
        __syncthreads();
    }

    // ---- epilogue ----
    const int g_  = lane >> 2;
    const int tig = lane & 3;
    #pragma unroll
    for (int nt = 0; nt < 4; nt++) {
        const int c = n0 + wn0 + nt * 8 + 2 * tig;
        float bv0 = 0.f, bv1 = 0.f;
        if (PROJ) { bv0 = bias[c]; bv1 = bias[c + 1]; }
        #pragma unroll
        for (int mt = 0; mt < 4; mt++) {
            const int r0 = m0 + wm0 + mt * 16 + g_;
            const int r1 = r0 + 8;
            if (PROJ) {
                float v00 = (acc[mt][nt][0] + bv0) * alpha;
                float v01 = (acc[mt][nt][1] + bv1) * alpha;
                float v10 = (acc[mt][nt][2] + bv0) * alpha;
                float v11 = (acc[mt][nt][3] + bv1) * alpha;
                __nv_bfloat162 h, l;
                split2(v00, v01, h, l);
                *(__nv_bfloat162*)(Chi + (size_t)r0 * ldc + c) = h;
                *(__nv_bfloat162*)(Clo + (size_t)r0 * ldc + c) = l;
                split2(v10, v11, h, l);
                *(__nv_bfloat162*)(Chi + (size_t)r1 * ldc + c) = h;
                *(__nv_bfloat162*)(Clo + (size_t)r1 * ldc + c) = l;
            } else {
                float2 o0 = { acc[mt][nt][0], acc[mt][nt][1] };
                float2 o1 = { acc[mt][nt][2], acc[mt][nt][3] };
                *(float2*)(Cf + (size_t)r0 * ldc + c) = o0;
                *(float2*)(Cf + (size_t)r1 * ldc + c) = o1;
            }
        }
    }
}

// ---------------- softmax: fp32 S row -> split bf16 P ----------------------
__global__ __launch_bounds__(256)
void softmax_split(const float* __restrict__ S,
                   __nv_bfloat16* __restrict__ Ph, __nv_bfloat16* __restrict__ Pl)
{
    const int row  = blockIdx.x;
    const int tid  = threadIdx.x;
    const int lane = tid & 31;
    const int wrp  = tid >> 5;
    const float4* p4 = (const float4*)(S + (size_t)row * MKV);

    float4 v[8];
    float m = -3.0e38f;
    #pragma unroll
    for (int i = 0; i < 8; i++) {
        v[i] = p4[tid + i * 256];
        m = fmaxf(m, fmaxf(fmaxf(v[i].x, v[i].y), fmaxf(v[i].z, v[i].w)));
    }

    __shared__ float red[8];
    #pragma unroll
    for (int s = 16; s > 0; s >>= 1)
        m = fmaxf(m, __shfl_xor_sync(0xffffffffu, m, s));
    if (lane == 0) red[wrp] = m;
    __syncthreads();
    m = red[lane & 7];
    #pragma unroll
    for (int s = 4; s > 0; s >>= 1)
        m = fmaxf(m, __shfl_xor_sync(0xffffffffu, m, s));
    m = __shfl_sync(0xffffffffu, m, 0);

    float sum = 0.0f;
    #pragma unroll
    for (int i = 0; i < 8; i++) {
        v[i].x = __expf(v[i].x - m);
        v[i].y = __expf(v[i].y - m);
        v[i].z = __expf(v[i].z - m);
        v[i].w = __expf(v[i].w - m);
        sum += (v[i].x + v[i].y) + (v[i].z + v[i].w);
    }
    #pragma unroll
    for (int s = 16; s > 0; s >>= 1)
        sum += __shfl_xor_sync(0xffffffffu, sum, s);
    __syncthreads();
    if (lane == 0) red[wrp] = sum;
    __syncthreads();
    sum = red[lane & 7];
    #pragma unroll
    for (int s = 4; s > 0; s >>= 1)
        sum += __shfl_xor_sync(0xffffffffu, sum, s);
    sum = __shfl_sync(0xffffffffu, sum, 0);
    const float inv = 1.0f / sum;

    __nv_bfloat162* h2 = (__nv_bfloat162*)(Ph + (size_t)row * MKV);
    __nv_bfloat162* l2 = (__nv_bfloat162*)(Pl + (size_t)row * MKV);
    #pragma unroll
    for (int i = 0; i < 8; i++) {
        const int idx = tid + i * 256;
        __nv_bfloat162 h, l;
        split2(v[i].x * inv, v[i].y * inv, h, l);
        h2[idx * 2]     = h;  l2[idx * 2]     = l;
        split2(v[i].z * inv, v[i].w * inv, h, l);
        h2[idx * 2 + 1] = h;  l2[idx * 2 + 1] = l;
    }
}

// ---------------------------------------------------------------------------
extern "C" void kernel_launch(void* const* d_in, const int* in_sizes, int n_in,
                              void* d_out, int out_size)
{
    const float* x   = (const float*)d_in[0];
    const float* ctx = (const float*)d_in[1];
    const float* Wq  = (const float*)d_in[2];
    const float* bq  = (const float*)d_in[3];
    const float* Wk  = (const float*)d_in[4];
    const float* bk  = (const float*)d_in[5];
    const float* Wv  = (const float*)d_in[6];
    const float* bv  = (const float*)d_in[7];
    float* out = (float*)d_out;

    __nv_bfloat16 *xh,*xl,*ch,*cl,*wqh,*wql,*wkh,*wkl,*wvh,*wvl;
    __nv_bfloat16 *qh,*ql,*kh,*kl,*vh,*vl,*ph,*pl;
    float* sp;
    cudaGetSymbolAddress((void**)&xh, g_xh);   cudaGetSymbolAddress((void**)&xl, g_xl);
    cudaGetSymbolAddress((void**)&ch, g_ch);   cudaGetSymbolAddress((void**)&cl, g_cl);
    cudaGetSymbolAddress((void**)&wqh, g_wqh); cudaGetSymbolAddress((void**)&wql, g_wql);
    cudaGetSymbolAddress((void**)&wkh, g_wkh); cudaGetSymbolAddress((void**)&wkl, g_wkl);
    cudaGetSymbolAddress((void**)&wvh, g_wvh); cudaGetSymbolAddress((void**)&wvl, g_wvl);
    cudaGetSymbolAddress((void**)&qh, g_qh);   cudaGetSymbolAddress((void**)&ql, g_ql);
    cudaGetSymbolAddress((void**)&kh, g_kh);   cudaGetSymbolAddress((void**)&kl, g_kl);
    cudaGetSymbolAddress((void**)&vh, g_vh);   cudaGetSymbolAddress((void**)&vl, g_vl);
    cudaGetSymbolAddress((void**)&ph, g_ph);   cudaGetSymbolAddress((void**)&pl, g_pl);
    cudaGetSymbolAddress((void**)&sp, g_s);

    cudaFuncSetAttribute(bgemm<false, true>,  cudaFuncAttributeMaxDynamicSharedMemorySize, 65536);
    cudaFuncSetAttribute(bgemm<true,  false>, cudaFuncAttributeMaxDynamicSharedMemorySize, 65536);
    cudaFuncSetAttribute(bgemm<false, false>, cudaFuncAttributeMaxDynamicSharedMemorySize, 65536);

    // 1) split fp32 inputs into hi/lo bf16
    splitk<<<(NQ  * DIMC / 4) / 256, 256>>>(x,   xh, xl, NQ  * DIMC / 4);
    splitk<<<(MKV * DIMC / 4) / 256, 256>>>(ctx, ch, cl, MKV * DIMC / 4);
    splitk<<<(DIMC * DIMC / 4) / 256, 256>>>(Wq, wqh, wql, DIMC * DIMC / 4);
    splitk<<<(DIMC * DIMC / 4) / 256, 256>>>(Wk, wkh, wkl, DIMC * DIMC / 4);
    splitk<<<(DIMC * DIMC / 4) / 256, 256>>>(Wv, wvh, wvl, DIMC * DIMC / 4);

    const float qscale = 1.0f / 32.0f;   // 1/sqrt(1024), folded into q

    // 2) projections (NN), outputs split bf16
    bgemm<false, true><<<dim3(DIMC/BN, NQ/BM),  256, 65536>>>(
        xh, xl, wqh, wql, DIMC, DIMC, DIMC, bq, qscale, nullptr, qh, ql, DIMC);
    bgemm<false, true><<<dim3(DIMC/BN, MKV/BM), 256, 65536>>>(
        ch, cl, wkh, wkl, DIMC, DIMC, DIMC, bk, 1.0f, nullptr, kh, kl, DIMC);
    bgemm<false, true><<<dim3(DIMC/BN, MKV/BM), 256, 65536>>>(
        ch, cl, wvh, wvl, DIMC, DIMC, DIMC, bv, 1.0f, nullptr, vh, vl, DIMC);

    // 3) scores S = q_scaled @ k^T (NT), fp32 out
    bgemm<true, false><<<dim3(MKV/BN, NQ/BM), 256, 65536>>>(
        qh, ql, kh, kl, DIMC, DIMC, DIMC, nullptr, 1.0f, sp, nullptr, nullptr, MKV);

    // 4) softmax rows -> split bf16 P
    softmax_split<<<NQ, 256>>>(sp, ph, pl);

    // 5) O = P @ v (NN), fp32 out
    bgemm<false, false><<<dim3(DIMC/BN, NQ/BM), 256, 65536>>>(
        ph, pl, vh, vl, MKV, DIMC, MKV, nullptr, 1.0f, out, nullptr, nullptr, DIMC);
}

// round 5
// speedup vs baseline: 3.0298x; 1.0171x over previous
#include <cuda_runtime.h>
#include <cuda_bf16.h>
#include <stdint.h>
#include <math.h>

constexpr int NQ   = 8192;
constexpr int MKV  = 8192;
constexpr int DIMC = 1024;

// ---------------- scratch (__device__ globals; allocation-free rule) --------
__device__ __nv_bfloat16 g_xh[(size_t)NQ*DIMC],  g_xl[(size_t)NQ*DIMC];
__device__ __nv_bfloat16 g_ch[(size_t)MKV*DIMC], g_cl[(size_t)MKV*DIMC];
__device__ __nv_bfloat16 g_wqh[(size_t)DIMC*DIMC], g_wql[(size_t)DIMC*DIMC];
__device__ __nv_bfloat16 g_wkh[(size_t)DIMC*DIMC], g_wkl[(size_t)DIMC*DIMC];
__device__ __nv_bfloat16 g_wvh[(size_t)DIMC*DIMC], g_wvl[(size_t)DIMC*DIMC];
__device__ __nv_bfloat16 g_qh[(size_t)NQ*DIMC],  g_ql[(size_t)NQ*DIMC];
__device__ __nv_bfloat16 g_kh[(size_t)MKV*DIMC], g_kl[(size_t)MKV*DIMC];
__device__ __nv_bfloat16 g_vh[(size_t)MKV*DIMC], g_vl[(size_t)MKV*DIMC];
__device__ float         g_s [(size_t)NQ*MKV];
__device__ __nv_bfloat16 g_ph[(size_t)NQ*MKV],  g_pl[(size_t)NQ*MKV];

// ---------------- PTX helpers ----------------------------------------------
__device__ __forceinline__ uint32_t s2u(const void* p) {
    uint32_t a;
    asm("{ .reg .u64 t; cvta.to.shared.u64 t, %1; cvt.u32.u64 %0, t; }"
        : "=r"(a) : "l"(p));
    return a;
}
#define CPASYNC16(sa, gp) \
    asm volatile("cp.async.cg.shared.global [%0], [%1], 16;" :: "r"(sa), "l"(gp))
#define CPCOMMIT() asm volatile("cp.async.commit_group;")
#define CPWAIT(n)  asm volatile("cp.async.wait_group %0;" :: "n"(n))

#define LDSM_X4(r0,r1,r2,r3,a) \
    asm volatile("ldmatrix.sync.aligned.m8n8.x4.shared.b16 {%0,%1,%2,%3}, [%4];" \
        : "=r"(r0),"=r"(r1),"=r"(r2),"=r"(r3) : "r"(a))
#define LDSM_X4_T(r0,r1,r2,r3,a) \
    asm volatile("ldmatrix.sync.aligned.m8n8.x4.trans.shared.b16 {%0,%1,%2,%3}, [%4];" \
        : "=r"(r0),"=r"(r1),"=r"(r2),"=r"(r3) : "r"(a))

#define MMA16816(c0,c1,c2,c3,a0,a1,a2,a3,b0,b1) \
    asm volatile("mma.sync.aligned.m16n8k16.row.col.f32.bf16.bf16.f32 " \
        "{%0,%1,%2,%3}, {%4,%5,%6,%7}, {%8,%9}, {%0,%1,%2,%3};" \
        : "+f"(c0),"+f"(c1),"+f"(c2),"+f"(c3) \
        : "r"(a0),"r"(a1),"r"(a2),"r"(a3), "r"(b0),"r"(b1))

__device__ __forceinline__ void split2(float a, float b,
                                       __nv_bfloat162& h, __nv_bfloat162& l) {
    __nv_bfloat16 ha = __float2bfloat16(a);
    __nv_bfloat16 hb = __float2bfloat16(b);
    h.x = ha; h.y = hb;
    l.x = __float2bfloat16(a - __bfloat162float(ha));
    l.y = __float2bfloat16(b - __bfloat162float(hb));
}

// ---------------- input split kernel (fp32 -> hi/lo bf16) -------------------
__global__ __launch_bounds__(256)
void splitk(const float* __restrict__ in, __nv_bfloat16* __restrict__ hi,
            __nv_bfloat16* __restrict__ lo, int n4)
{
    int i = blockIdx.x * 256 + threadIdx.x;
    if (i >= n4) return;
    float4 v = ((const float4*)in)[i];
    __nv_bfloat162 h0, l0, h1, l1;
    split2(v.x, v.y, h0, l0);
    split2(v.z, v.w, h1, l1);
    ((__nv_bfloat162*)hi)[2*i]   = h0;
    ((__nv_bfloat162*)hi)[2*i+1] = h1;
    ((__nv_bfloat162*)lo)[2*i]   = l0;
    ((__nv_bfloat162*)lo)[2*i+1] = l1;
}

// ---------------- fused split-bf16 GEMM ------------------------------------
// C[M,N] = Ahi@op(Bhi) + Alo@op(Bhi) + Ahi@op(Blo), one fused k-loop,
// all three products accumulate into the same fp32 accumulator.
// A: [M,K] row-major bf16.  TRANS_B ? B:[N,K] : B:[K,N] row-major bf16.
constexpr int BM = 128, BN = 128, BK = 64;
// per-stage smem layout (bytes): Ah@0 Al@16K Bh@32K Bl@48K ; stage=64KB
constexpr uint32_t OFF_AL = 16384, OFF_BH = 32768, OFF_BL = 49152;
constexpr uint32_t STAGE  = 65536;
constexpr uint32_t SMEM_TOTAL = 2 * STAGE;   // 128 KB

template<bool TRANS_B, bool PROJ>
__global__ __launch_bounds__(256, 1)
void bgemm(const __nv_bfloat16* __restrict__ Ahi, const __nv_bfloat16* __restrict__ Alo,
           const __nv_bfloat16* __restrict__ Bhi, const __nv_bfloat16* __restrict__ Blo,
           int lda, int ldb, int K,
           const float* __restrict__ bias, float alpha,
           float* __restrict__ Cf,
           __nv_bfloat16* __restrict__ Chi, __nv_bfloat16* __restrict__ Clo,
           int ldc)
{
    extern __shared__ char smem[];
    const uint32_t sS = s2u(smem);

    const int tid  = threadIdx.x;
    const int lane = tid & 31;
    const int wid  = tid >> 5;
    const int wm0  = (wid >> 2) * 64;         // warp m offset
    const int wn0  = (wid & 3) * 32;          // warp n offset
    const int m0   = blockIdx.y * BM;
    const int n0   = blockIdx.x * BN;

    // ---- global->smem loader geometry ----
    // A tiles: 128 rows x 64 cols = rows of 128B = 8 chunks of 16B
    const int aRow0  = tid >> 3;              // +32*i
    const int aChunk = tid & 7;
    const uint32_t aSoff = (uint32_t)aRow0 * 128 + ((aChunk ^ (aRow0 & 7)) << 4);
    // B tiles: NT 128x64 (128B rows); NN 64x128 (256B rows, 16 chunks)
    const int bRow0  = TRANS_B ? (tid >> 3) : (tid >> 4);
    const int bChunk = TRANS_B ? (tid & 7)  : (tid & 15);
    const uint32_t bSoff = TRANS_B
        ? ((uint32_t)bRow0 * 128 + ((bChunk ^ (bRow0 & 7)) << 4))
        : ((uint32_t)bRow0 * 256 + ((bChunk ^ (bRow0 & 7)) << 4));

    auto load_stage = [&](int stage, int k0) {
        const uint32_t sb = sS + (uint32_t)stage * STAGE;
        // A hi + lo
        const __nv_bfloat16* gAh = Ahi + (size_t)(m0 + aRow0) * lda + k0 + aChunk * 8;
        const __nv_bfloat16* gAl = Alo + (size_t)(m0 + aRow0) * lda + k0 + aChunk * 8;
        #pragma unroll
        for (int i = 0; i < 4; i++) {
            CPASYNC16(sb + aSoff + i * 4096,          gAh + (size_t)32 * i * lda);
            CPASYNC16(sb + OFF_AL + aSoff + i * 4096, gAl + (size_t)32 * i * lda);
        }
        // B hi + lo
        if (TRANS_B) {
            const __nv_bfloat16* gBh = Bhi + (size_t)(n0 + bRow0) * ldb + k0 + bChunk * 8;
            const __nv_bfloat16* gBl = Blo + (size_t)(n0 + bRow0) * ldb + k0 + bChunk * 8;
            #pragma unroll
            for (int i = 0; i < 4; i++) {
                CPASYNC16(sb + OFF_BH + bSoff + i * 4096, gBh + (size_t)32 * i * ldb);
                CPASYNC16(sb + OFF_BL + bSoff + i * 4096, gBl + (size_t)32 * i * ldb);
            }
        } else {
            const __nv_bfloat16* gBh = Bhi + (size_t)(k0 + bRow0) * ldb + n0 + bChunk * 8;
            const __nv_bfloat16* gBl = Blo + (size_t)(k0 + bRow0) * ldb + n0 + bChunk * 8;
            #pragma unroll
            for (int i = 0; i < 4; i++) {
                CPASYNC16(sb + OFF_BH + bSoff + i * 4096, gBh + (size_t)16 * i * ldb);
                CPASYNC16(sb + OFF_BL + bSoff + i * 4096, gBl + (size_t)16 * i * ldb);
            }
        }
    };

    // ---- mma fragment geometry (identical to verified R3 layout) ----
    const int sub  = lane >> 3;
    const int roct = lane & 7;

    int arow[4];
    #pragma unroll
    for (int mt = 0; mt < 4; mt++)
        arow[mt] = wm0 + mt * 16 + (sub & 1) * 8 + roct;

    int nrow[2];
    uint32_t bnnBase[2];
    #pragma unroll
    for (int np = 0; np < 2; np++) {
        nrow[np] = wn0 + np * 16 + (sub >> 1) * 8 + roct;
        int nch  = (wn0 >> 3) + np * 2 + (sub >> 1);
        bnnBase[np] = (uint32_t)(((sub & 1) * 8 + roct) * 256) + ((nch ^ roct) << 4);
    }

    float acc[4][4][4];
    #pragma unroll
    for (int mt = 0; mt < 4; mt++)
        #pragma unroll
        for (int nt = 0; nt < 4; nt++)
            #pragma unroll
            for (int e = 0; e < 4; e++)
                acc[mt][nt][e] = 0.0f;

    const int nkt = K >> 6;
    load_stage(0, 0);
    CPCOMMIT();

    for (int it = 0; it < nkt; ++it) {
        if (it + 1 < nkt) {
            load_stage((it + 1) & 1, (it + 1) * BK);
            CPCOMMIT();
            CPWAIT(1);
        } else {
            CPWAIT(0);
        }
        __syncthreads();

        const uint32_t sb    = sS + (uint32_t)(it & 1) * STAGE;
        const uint32_t aBaseH = sb;
        const uint32_t aBaseL = sb + OFF_AL;
        const uint32_t bBaseH = sb + OFF_BH;
        const uint32_t bBaseL = sb + OFF_BL;

        #pragma unroll
        for (int kk = 0; kk < 4; kk++) {
            // A hi fragments
            uint32_t ah[4][4], al[4][4];
            #pragma unroll
            for (int mt = 0; mt < 4; mt++) {
                const int kch = kk * 2 + (sub >> 1);
                const uint32_t off = (uint32_t)arow[mt] * 128 + ((kch ^ (arow[mt] & 7)) << 4);
                LDSM_X4(ah[mt][0], ah[mt][1], ah[mt][2], ah[mt][3], aBaseH + off);
                LDSM_X4(al[mt][0], al[mt][1], al[mt][2], al[mt][3], aBaseL + off);
            }
            // B hi + lo fragments
            uint32_t bh[2][4], bl[2][4];
            #pragma unroll
            for (int np = 0; np < 2; np++) {
                if (TRANS_B) {
                    const int kch = kk * 2 + (sub & 1);
                    const uint32_t off = (uint32_t)nrow[np] * 128 + ((kch ^ (nrow[np] & 7)) << 4);
                    LDSM_X4(bh[np][0], bh[np][1], bh[np][2], bh[np][3], bBaseH + off);
                    LDSM_X4(bl[np][0], bl[np][1], bl[np][2], bl[np][3], bBaseL + off);
                } else {
                    const uint32_t off = (uint32_t)kk * 4096 + bnnBase[np];
                    LDSM_X4_T(bh[np][0], bh[np][1], bh[np][2], bh[np][3], bBaseH + off);
                    LDSM_X4_T(bl[np][0], bl[np][1], bl[np][2], bl[np][3], bBaseL + off);
                }
            }
            // three fused passes into the same accumulator
            #pragma unroll
            for (int mt = 0; mt < 4; mt++) {
                #pragma unroll
                for (int nt = 0; nt < 4; nt++) {
                    uint32_t h0 = bh[nt >> 1][(nt & 1) * 2];
                    uint32_t h1 = bh[nt >> 1][(nt & 1) * 2 + 1];
                    uint32_t l0 = bl[nt >> 1][(nt & 1) * 2];
                    uint32_t l1 = bl[nt >> 1][(nt & 1) * 2 + 1];
                    MMA16816(acc[mt][nt][0], acc[mt][nt][1], acc[mt][nt][2], acc[mt][nt][3],
                             ah[mt][0], ah[mt][1], ah[mt][2], ah[mt][3], h0, h1);
                    MMA16816(acc[mt][nt][0], acc[mt][nt][1], acc[mt][nt][2], acc[mt][nt][3],
                             al[mt][0], al[mt][1], al[mt][2], al[mt][3], h0, h1);
                    MMA16816(acc[mt][nt][0], acc[mt][nt][1], acc[mt][nt][2], acc[mt][nt][3],
                             ah[mt][0], ah[mt][1], ah[mt][2], ah[mt][3], l0, l1);
                }
            }
        }
        __syncthreads();
    }

    // ---- epilogue ----
    const int g_  = lane >> 2;
    const int tig = lane & 3;
    #pragma unroll
    for (int nt = 0; nt < 4; nt++) {
        const int c = n0 + wn0 + nt * 8 + 2 * tig;
        float bv0 = 0.f, bv1 = 0.f;
        if (PROJ) { bv0 = bias[c]; bv1 = bias[c + 1]; }
        #pragma unroll
        for (int mt = 0; mt < 4; mt++) {
            const int r0 = m0 + wm0 + mt * 16 + g_;
            const int r1 = r0 + 8;
            if (PROJ) {
                float v00 = (acc[mt][nt][0] + bv0) * alpha;
                float v01 = (acc[mt][nt][1] + bv1) * alpha;
                float v10 = (acc[mt][nt][2] + bv0) * alpha;
                float v11 = (acc[mt][nt][3] + bv1) * alpha;
                __nv_bfloat162 h, l;
                split2(v00, v01, h, l);
                *(__nv_bfloat162*)(Chi + (size_t)r0 * ldc + c) = h;
                *(__nv_bfloat162*)(Clo + (size_t)r0 * ldc + c) = l;
                split2(v10, v11, h, l);
                *(__nv_bfloat162*)(Chi + (size_t)r1 * ldc + c) = h;
                *(__nv_bfloat162*)(Clo + (size_t)r1 * ldc + c) = l;
            } else {
                float2 o0 = { acc[mt][nt][0], acc[mt][nt][1] };
                float2 o1 = { acc[mt][nt][2], acc[mt][nt][3] };
                *(float2*)(Cf + (size_t)r0 * ldc + c) = o0;
                *(float2*)(Cf + (size_t)r1 * ldc + c) = o1;
            }
        }
    }
}

// ---------------- softmax: fp32 S row -> split bf16 P ----------------------
__global__ __launch_bounds__(256)
void softmax_split(const float* __restrict__ S,
                   __nv_bfloat16* __restrict__ Ph, __nv_bfloat16* __restrict__ Pl)
{
    const int row  = blockIdx.x;
    const int tid  = threadIdx.x;
    const int lane = tid & 31;
    const int wrp  = tid >> 5;
    const float4* p4 = (const float4*)(S + (size_t)row * MKV);

    float4 v[8];
    float m = -3.0e38f;
    #pragma unroll
    for (int i = 0; i < 8; i++) {
        v[i] = p4[tid + i * 256];
        m = fmaxf(m, fmaxf(fmaxf(v[i].x, v[i].y), fmaxf(v[i].z, v[i].w)));
    }
    __shared__ float red[8];
    #pragma unroll
    for (int s = 16; s > 0; s >>= 1) m = fmaxf(m, __shfl_xor_sync(~0u, m, s));
    if (lane == 0) red[wrp] = m;
    __syncthreads();
    m = red[lane & 7];
    #pragma unroll
    for (int s = 4; s > 0; s >>= 1) m = fmaxf(m, __shfl_xor_sync(~0u, m, s));
    m = __shfl_sync(~0u, m, 0);

    float sum = 0.0f;
    #pragma unroll
    for (int i = 0; i < 8; i++) {
        v[i].x = __expf(v[i].x - m); v[i].y = __expf(v[i].y - m);
        v[i].z = __expf(v[i].z - m); v[i].w = __expf(v[i].w - m);
        sum += (v[i].x + v[i].y) + (v[i].z + v[i].w);
    }
    #pragma unroll
    for (int s = 16; s > 0; s >>= 1) sum += __shfl_xor_sync(~0u, sum, s);
    __syncthreads();
    if (lane == 0) red[wrp] = sum;
    __syncthreads();
    sum = red[lane & 7];
    #pragma unroll
    for (int s = 4; s > 0; s >>= 1) sum += __shfl_xor_sync(~0u, sum, s);
    sum = __shfl_sync(~0u, sum, 0);
    const float inv = 1.0f / sum;

    __nv_bfloat162* h2 = (__nv_bfloat162*)(Ph + (size_t)row * MKV);
    __nv_bfloat162* l2 = (__nv_bfloat162*)(Pl + (size_t)row * MKV);
    #pragma unroll
    for (int i = 0; i < 8; i++) {
        const int idx = tid + i * 256;
        __nv_bfloat162 h, l;
        split2(v[i].x * inv, v[i].y * inv, h, l);
        h2[idx*2]   = h;  l2[idx*2]   = l;
        split2(v[i].z * inv, v[i].w * inv, h, l);
        h2[idx*2+1] = h;  l2[idx*2+1] = l;
    }
}

// ---------------------------------------------------------------------------
extern "C" void kernel_launch(void* const* d_in, const int* in_sizes, int n_in,
                              void* d_out, int out_size)
{
    const float* x   = (const float*)d_in[0];
    const float* ctx = (const float*)d_in[1];
    const float* Wq  = (const float*)d_in[2];
    const float* bq  = (const float*)d_in[3];
    const float* Wk  = (const float*)d_in[4];
    const float* bk  = (const float*)d_in[5];
    const float* Wv  = (const float*)d_in[6];
    const float* bv  = (const float*)d_in[7];
    float* out = (float*)d_out;

    __nv_bfloat16 *xh,*xl,*ch,*cl,*wqh,*wql,*wkh,*wkl,*wvh,*wvl;
    __nv_bfloat16 *qh,*ql,*kh,*kl,*vh,*vl,*ph,*pl;
    float* sp;
    cudaGetSymbolAddress((void**)&xh, g_xh);   cudaGetSymbolAddress((void**)&xl, g_xl);
    cudaGetSymbolAddress((void**)&ch, g_ch);   cudaGetSymbolAddress((void**)&cl, g_cl);
    cudaGetSymbolAddress((void**)&wqh, g_wqh); cudaGetSymbolAddress((void**)&wql, g_wql);
    cudaGetSymbolAddress((void**)&wkh, g_wkh); cudaGetSymbolAddress((void**)&wkl, g_wkl);
    cudaGetSymbolAddress((void**)&wvh, g_wvh); cudaGetSymbolAddress((void**)&wvl, g_wvl);
    cudaGetSymbolAddress((void**)&qh, g_qh);   cudaGetSymbolAddress((void**)&ql, g_ql);
    cudaGetSymbolAddress((void**)&kh, g_kh);   cudaGetSymbolAddress((void**)&kl, g_kl);
    cudaGetSymbolAddress((void**)&vh, g_vh);   cudaGetSymbolAddress((void**)&vl, g_vl);
    cudaGetSymbolAddress((void**)&ph, g_ph);   cudaGetSymbolAddress((void**)&pl, g_pl);
    cudaGetSymbolAddress((void**)&sp, g_s);

    cudaFuncSetAttribute(bgemm<false, true>,  cudaFuncAttributeMaxDynamicSharedMemorySize, SMEM_TOTAL);
    cudaFuncSetAttribute(bgemm<true,  false>, cudaFuncAttributeMaxDynamicSharedMemorySize, SMEM_TOTAL);
    cudaFuncSetAttribute(bgemm<false, false>, cudaFuncAttributeMaxDynamicSharedMemorySize, SMEM_TOTAL);

    // 1) split fp32 inputs into hi/lo bf16
    splitk<<<(NQ  * DIMC / 4) / 256, 256>>>(x,   xh, xl, NQ  * DIMC / 4);
    splitk<<<(MKV * DIMC / 4) / 256, 256>>>(ctx, ch, cl, MKV * DIMC / 4);
    splitk<<<(DIMC * DIMC / 4) / 256, 256>>>(Wq, wqh, wql, DIMC * DIMC / 4);
    splitk<<<(DIMC * DIMC / 4) / 256, 256>>>(Wk, wkh, wkl, DIMC * DIMC / 4);
    splitk<<<(DIMC * DIMC / 4) / 256, 256>>>(Wv, wvh, wvl, DIMC * DIMC / 4);

    const float qscale = 1.0f / 32.0f;   // 1/sqrt(1024), folded into q

    // 2) projections (NN), outputs split bf16
    bgemm<false, true><<<dim3(DIMC/BN, NQ/BM),  256, SMEM_TOTAL>>>(
        xh, xl, wqh, wql, DIMC, DIMC, DIMC, bq, qscale, nullptr, qh, ql, DIMC);
    bgemm<false, true><<<dim3(DIMC/BN, MKV/BM), 256, SMEM_TOTAL>>>(
        ch, cl, wkh, wkl, DIMC, DIMC, DIMC, bk, 1.0f, nullptr, kh, kl, DIMC);
    bgemm<false, true><<<dim3(DIMC/BN, MKV/BM), 256, SMEM_TOTAL>>>(
        ch, cl, wvh, wvl, DIMC, DIMC, DIMC, bv, 1.0f, nullptr, vh, vl, DIMC);

    // 3) scores S = q_scaled @ k^T (NT), fp32 out
    bgemm<true, false><<<dim3(MKV/BN, NQ/BM), 256, SMEM_TOTAL>>>(
        qh, ql, kh, kl, DIMC, DIMC, DIMC, nullptr, 1.0f, sp, nullptr, nullptr, MKV);

    // 4) softmax rows -> split bf16 P
    softmax_split<<<NQ, 256>>>(sp, ph, pl);

    // 5) O = P @ v (NN), fp32 out
    bgemm<false, false><<<dim3(DIMC/BN, NQ/BM), 256, SMEM_TOTAL>>>(
        ph, pl, vh, vl, MKV, DIMC, MKV, nullptr, 1.0f, out, nullptr, nullptr, DIMC);
}

// round 6
// speedup vs baseline: 4.7394x; 1.5643x over previous
#include <cuda_runtime.h>
#include <cuda_fp16.h>
#include <stdint.h>
#include <math.h>

constexpr int NQ   = 8192;
constexpr int MKV  = 8192;
constexpr int DIMC = 1024;

// ---------------- scratch (__device__ globals; allocation-free rule) --------
__device__ __half g_xh[(size_t)NQ*DIMC],  g_xl[(size_t)NQ*DIMC];
__device__ __half g_ch[(size_t)MKV*DIMC], g_cl[(size_t)MKV*DIMC];
__device__ __half g_wqh[(size_t)DIMC*DIMC];
__device__ __half g_wkh[(size_t)DIMC*DIMC];
__device__ __half g_wvh[(size_t)DIMC*DIMC];
__device__ __half g_qh[(size_t)NQ*DIMC],  g_ql[(size_t)NQ*DIMC];
__device__ __half g_kh[(size_t)MKV*DIMC], g_kl[(size_t)MKV*DIMC];
__device__ __half g_vh[(size_t)MKV*DIMC], g_vl[(size_t)MKV*DIMC];
__device__ float  g_s [(size_t)NQ*MKV];
__device__ __half g_ph[(size_t)NQ*MKV],  g_pl[(size_t)NQ*MKV];

// ---------------- PTX helpers ----------------------------------------------
__device__ __forceinline__ uint32_t s2u(const void* p) {
    uint32_t a;
    asm("{ .reg .u64 t; cvta.to.shared.u64 t, %1; cvt.u32.u64 %0, t; }"
        : "=r"(a) : "l"(p));
    return a;
}
#define CPASYNC16(sa, gp) \
    asm volatile("cp.async.cg.shared.global [%0], [%1], 16;" :: "r"(sa), "l"(gp))
#define CPCOMMIT() asm volatile("cp.async.commit_group;")
#define CPWAIT(n)  asm volatile("cp.async.wait_group %0;" :: "n"(n))

#define LDSM_X4(r0,r1,r2,r3,a) \
    asm volatile("ldmatrix.sync.aligned.m8n8.x4.shared.b16 {%0,%1,%2,%3}, [%4];" \
        : "=r"(r0),"=r"(r1),"=r"(r2),"=r"(r3) : "r"(a))
#define LDSM_X4_T(r0,r1,r2,r3,a) \
    asm volatile("ldmatrix.sync.aligned.m8n8.x4.trans.shared.b16 {%0,%1,%2,%3}, [%4];" \
        : "=r"(r0),"=r"(r1),"=r"(r2),"=r"(r3) : "r"(a))

#define MMA16816(c0,c1,c2,c3,a0,a1,a2,a3,b0,b1) \
    asm volatile("mma.sync.aligned.m16n8k16.row.col.f32.f16.f16.f32 " \
        "{%0,%1,%2,%3}, {%4,%5,%6,%7}, {%8,%9}, {%0,%1,%2,%3};" \
        : "+f"(c0),"+f"(c1),"+f"(c2),"+f"(c3) \
        : "r"(a0),"r"(a1),"r"(a2),"r"(a3), "r"(b0),"r"(b1))

__device__ __forceinline__ void split2h(float a, float b, __half2& h, __half2& l) {
    __half ha = __float2half_rn(a);
    __half hb = __float2half_rn(b);
    h = __halves2half2(ha, hb);
    l = __halves2half2(__float2half_rn(a - __half2float(ha)),
                       __float2half_rn(b - __half2float(hb)));
}

// ---------------- split kernels (fp32 -> hi/lo fp16) ------------------------
__global__ __launch_bounds__(256)
void splitk(const float* __restrict__ in, __half* __restrict__ hi,
            __half* __restrict__ lo, int n4)
{
    int i = blockIdx.x * 256 + threadIdx.x;
    if (i >= n4) return;
    float4 v = ((const float4*)in)[i];
    __half2 h0, l0, h1, l1;
    split2h(v.x, v.y, h0, l0);
    split2h(v.z, v.w, h1, l1);
    ((__half2*)hi)[2*i]   = h0;
    ((__half2*)hi)[2*i+1] = h1;
    ((__half2*)lo)[2*i]   = l0;
    ((__half2*)lo)[2*i+1] = l1;
}

__global__ __launch_bounds__(256)
void splitk_hi(const float* __restrict__ in, __half* __restrict__ hi, int n4)
{
    int i = blockIdx.x * 256 + threadIdx.x;
    if (i >= n4) return;
    float4 v = ((const float4*)in)[i];
    __half2 h0 = __halves2half2(__float2half_rn(v.x), __float2half_rn(v.y));
    __half2 h1 = __halves2half2(__float2half_rn(v.z), __float2half_rn(v.w));
    ((__half2*)hi)[2*i]   = h0;
    ((__half2*)hi)[2*i+1] = h1;
}

// ---------------- fused 2-pass fp16 split GEMM ------------------------------
// C[M,N] = (Ahi + Alo) @ op(Bhi)   — A residual kept, B residual dropped.
// A: [M,K] row-major fp16.  TRANS_B ? B:[N,K] : B:[K,N] row-major fp16.
// PROJ: {Chi,Clo} = split(acc + bias[col]);  else Cf = acc * alpha.
constexpr int BM = 128, BN = 128, BK = 64;
// per-stage smem (bytes): Ah@0  Al@16K  Bh@32K ; stage = 48KB
constexpr uint32_t OFF_AL = 16384, OFF_BH = 32768;
constexpr uint32_t STAGE  = 49152;
constexpr uint32_t SMEM_TOTAL = 2 * STAGE;   // 96 KB

template<bool TRANS_B, bool PROJ>
__global__ __launch_bounds__(256, 2)
void hgemm(const __half* __restrict__ Ahi, const __half* __restrict__ Alo,
           const __half* __restrict__ Bhi,
           int lda, int ldb, int K,
           const float* __restrict__ bias, float alpha,
           float* __restrict__ Cf,
           __half* __restrict__ Chi, __half* __restrict__ Clo,
           int ldc)
{
    extern __shared__ char smem[];
    const uint32_t sS = s2u(smem);

    const int tid  = threadIdx.x;
    const int lane = tid & 31;
    const int wid  = tid >> 5;
    const int wm0  = (wid >> 2) * 64;
    const int wn0  = (wid & 3) * 32;
    const int m0   = blockIdx.y * BM;
    const int n0   = blockIdx.x * BN;

    // ---- global->smem loader geometry ----
    const int aRow0  = tid >> 3;
    const int aChunk = tid & 7;
    const uint32_t aSoff = (uint32_t)aRow0 * 128 + ((aChunk ^ (aRow0 & 7)) << 4);
    const int bRow0  = TRANS_B ? (tid >> 3) : (tid >> 4);
    const int bChunk = TRANS_B ? (tid & 7)  : (tid & 15);
    const uint32_t bSoff = TRANS_B
        ? ((uint32_t)bRow0 * 128 + ((bChunk ^ (bRow0 & 7)) << 4))
        : ((uint32_t)bRow0 * 256 + ((bChunk ^ (bRow0 & 7)) << 4));

    auto load_stage = [&](int stage, int k0) {
        const uint32_t sb = sS + (uint32_t)stage * STAGE;
        const __half* gAh = Ahi + (size_t)(m0 + aRow0) * lda + k0 + aChunk * 8;
        const __half* gAl = Alo + (size_t)(m0 + aRow0) * lda + k0 + aChunk * 8;
        #pragma unroll
        for (int i = 0; i < 4; i++) {
            CPASYNC16(sb + aSoff + i * 4096,          gAh + (size_t)32 * i * lda);
            CPASYNC16(sb + OFF_AL + aSoff + i * 4096, gAl + (size_t)32 * i * lda);
        }
        if (TRANS_B) {
            const __half* gBh = Bhi + (size_t)(n0 + bRow0) * ldb + k0 + bChunk * 8;
            #pragma unroll
            for (int i = 0; i < 4; i++)
                CPASYNC16(sb + OFF_BH + bSoff + i * 4096, gBh + (size_t)32 * i * ldb);
        } else {
            const __half* gBh = Bhi + (size_t)(k0 + bRow0) * ldb + n0 + bChunk * 8;
            #pragma unroll
            for (int i = 0; i < 4; i++)
                CPASYNC16(sb + OFF_BH + bSoff + i * 4096, gBh + (size_t)16 * i * ldb);
        }
    };

    // ---- mma fragment geometry (verified layout from R3/R5) ----
    const int sub  = lane >> 3;
    const int roct = lane & 7;

    int arow[4];
    #pragma unroll
    for (int mt = 0; mt < 4; mt++)
        arow[mt] = wm0 + mt * 16 + (sub & 1) * 8 + roct;

    int nrow[2];
    uint32_t bnnBase[2];
    #pragma unroll
    for (int np = 0; np < 2; np++) {
        nrow[np] = wn0 + np * 16 + (sub >> 1) * 8 + roct;
        int nch  = (wn0 >> 3) + np * 2 + (sub >> 1);
        bnnBase[np] = (uint32_t)(((sub & 1) * 8 + roct) * 256) + ((nch ^ roct) << 4);
    }

    float acc[4][4][4];
    #pragma unroll
    for (int mt = 0; mt < 4; mt++)
        #pragma unroll
        for (int nt = 0; nt < 4; nt++)
            #pragma unroll
            for (int e = 0; e < 4; e++)
                acc[mt][nt][e] = 0.0f;

    const int nkt = K >> 6;
    load_stage(0, 0);
    CPCOMMIT();

    for (int it = 0; it < nkt; ++it) {
        if (it + 1 < nkt) {
            load_stage((it + 1) & 1, (it + 1) * BK);
            CPCOMMIT();
            CPWAIT(1);
        } else {
            CPWAIT(0);
        }
        __syncthreads();

        const uint32_t sb     = sS + (uint32_t)(it & 1) * STAGE;
        const uint32_t aBaseH = sb;
        const uint32_t aBaseL = sb + OFF_AL;
        const uint32_t bBaseH = sb + OFF_BH;

        #pragma unroll
        for (int kk = 0; kk < 4; kk++) {
            uint32_t ah[4][4], al[4][4];
            #pragma unroll
            for (int mt = 0; mt < 4; mt++) {
                const int kch = kk * 2 + (sub >> 1);
                const uint32_t off = (uint32_t)arow[mt] * 128 + ((kch ^ (arow[mt] & 7)) << 4);
                LDSM_X4(ah[mt][0], ah[mt][1], ah[mt][2], ah[mt][3], aBaseH + off);
                LDSM_X4(al[mt][0], al[mt][1], al[mt][2], al[mt][3], aBaseL + off);
            }
            uint32_t bh[2][4];
            #pragma unroll
            for (int np = 0; np < 2; np++) {
                if (TRANS_B) {
                    const int kch = kk * 2 + (sub & 1);
                    const uint32_t off = (uint32_t)nrow[np] * 128 + ((kch ^ (nrow[np] & 7)) << 4);
                    LDSM_X4(bh[np][0], bh[np][1], bh[np][2], bh[np][3], bBaseH + off);
                } else {
                    const uint32_t off = (uint32_t)kk * 4096 + bnnBase[np];
                    LDSM_X4_T(bh[np][0], bh[np][1], bh[np][2], bh[np][3], bBaseH + off);
                }
            }
            #pragma unroll
            for (int mt = 0; mt < 4; mt++) {
                #pragma unroll
                for (int nt = 0; nt < 4; nt++) {
                    uint32_t h0 = bh[nt >> 1][(nt & 1) * 2];
                    uint32_t h1 = bh[nt >> 1][(nt & 1) * 2 + 1];
                    MMA16816(acc[mt][nt][0], acc[mt][nt][1], acc[mt][nt][2], acc[mt][nt][3],
                             ah[mt][0], ah[mt][1], ah[mt][2], ah[mt][3], h0, h1);
                    MMA16816(acc[mt][nt][0], acc[mt][nt][1], acc[mt][nt][2], acc[mt][nt][3],
                             al[mt][0], al[mt][1], al[mt][2], al[mt][3], h0, h1);
                }
            }
        }
        __syncthreads();
    }

    // ---- epilogue ----
    const int g_  = lane >> 2;
    const int tig = lane & 3;
    #pragma unroll
    for (int nt = 0; nt < 4; nt++) {
        const int c = n0 + wn0 + nt * 8 + 2 * tig;
        float bv0 = 0.f, bv1 = 0.f;
        if (PROJ) { bv0 = bias[c]; bv1 = bias[c + 1]; }
        #pragma unroll
        for (int mt = 0; mt < 4; mt++) {
            const int r0 = m0 + wm0 + mt * 16 + g_;
            const int r1 = r0 + 8;
            if (PROJ) {
                float v00 = acc[mt][nt][0] + bv0;
                float v01 = acc[mt][nt][1] + bv1;
                float v10 = acc[mt][nt][2] + bv0;
                float v11 = acc[mt][nt][3] + bv1;
                __half2 h, l;
                split2h(v00, v01, h, l);
                *(__half2*)(Chi + (size_t)r0 * ldc + c) = h;
                *(__half2*)(Clo + (size_t)r0 * ldc + c) = l;
                split2h(v10, v11, h, l);
                *(__half2*)(Chi + (size_t)r1 * ldc + c) = h;
                *(__half2*)(Clo + (size_t)r1 * ldc + c) = l;
            } else {
                float2 o0 = { acc[mt][nt][0] * alpha, acc[mt][nt][1] * alpha };
                float2 o1 = { acc[mt][nt][2] * alpha, acc[mt][nt][3] * alpha };
                *(float2*)(Cf + (size_t)r0 * ldc + c) = o0;
                *(float2*)(Cf + (size_t)r1 * ldc + c) = o1;
            }
        }
    }
}

// ---------------- softmax: fp32 S row -> split fp16 P (x512) ----------------
__global__ __launch_bounds__(256)
void softmax_split(const float* __restrict__ S,
                   __half* __restrict__ Ph, __half* __restrict__ Pl)
{
    const int row  = blockIdx.x;
    const int tid  = threadIdx.x;
    const int lane = tid & 31;
    const int wrp  = tid >> 5;
    const float4* p4 = (const float4*)(S + (size_t)row * MKV);

    float4 v[8];
    float m = -3.0e38f;
    #pragma unroll
    for (int i = 0; i < 8; i++) {
        v[i] = p4[tid + i * 256];
        m = fmaxf(m, fmaxf(fmaxf(v[i].x, v[i].y), fmaxf(v[i].z, v[i].w)));
    }
    __shared__ float red[8];
    #pragma unroll
    for (int s = 16; s > 0; s >>= 1) m = fmaxf(m, __shfl_xor_sync(~0u, m, s));
    if (lane == 0) red[wrp] = m;
    __syncthreads();
    m = red[lane & 7];
    #pragma unroll
    for (int s = 4; s > 0; s >>= 1) m = fmaxf(m, __shfl_xor_sync(~0u, m, s));
    m = __shfl_sync(~0u, m, 0);

    float sum = 0.0f;
    #pragma unroll
    for (int i = 0; i < 8; i++) {
        v[i].x = __expf(v[i].x - m); v[i].y = __expf(v[i].y - m);
        v[i].z = __expf(v[i].z - m); v[i].w = __expf(v[i].w - m);
        sum += (v[i].x + v[i].y) + (v[i].z + v[i].w);
    }
    #pragma unroll
    for (int s = 16; s > 0; s >>= 1) sum += __shfl_xor_sync(~0u, sum, s);
    __syncthreads();
    if (lane == 0) red[wrp] = sum;
    __syncthreads();
    sum = red[lane & 7];
    #pragma unroll
    for (int s = 4; s > 0; s >>= 1) sum += __shfl_xor_sync(~0u, sum, s);
    sum = __shfl_sync(~0u, sum, 0);
    const float inv = 512.0f / sum;   // x512 keeps P out of fp16 subnormals

    __half2* h2 = (__half2*)(Ph + (size_t)row * MKV);
    __half2* l2 = (__half2*)(Pl + (size_t)row * MKV);
    #pragma unroll
    for (int i = 0; i < 8; i++) {
        const int idx = tid + i * 256;
        __half2 h, l;
        split2h(v[i].x * inv, v[i].y * inv, h, l);
        h2[idx*2]   = h;  l2[idx*2]   = l;
        split2h(v[i].z * inv, v[i].w * inv, h, l);
        h2[idx*2+1] = h;  l2[idx*2+1] = l;
    }
}

// ---------------------------------------------------------------------------
extern "C" void kernel_launch(void* const* d_in, const int* in_sizes, int n_in,
                              void* d_out, int out_size)
{
    const float* x   = (const float*)d_in[0];
    const float* ctx = (const float*)d_in[1];
    const float* Wq  = (const float*)d_in[2];
    const float* bq  = (const float*)d_in[3];
    const float* Wk  = (const float*)d_in[4];
    const float* bk  = (const float*)d_in[5];
    const float* Wv  = (const float*)d_in[6];
    const float* bv  = (const float*)d_in[7];
    float* out = (float*)d_out;

    __half *xh,*xl,*ch,*cl,*wqh,*wkh,*wvh;
    __half *qh,*ql,*kh,*kl,*vh,*vl,*ph,*pl;
    float* sp;
    cudaGetSymbolAddress((void**)&xh, g_xh);   cudaGetSymbolAddress((void**)&xl, g_xl);
    cudaGetSymbolAddress((void**)&ch, g_ch);   cudaGetSymbolAddress((void**)&cl, g_cl);
    cudaGetSymbolAddress((void**)&wqh, g_wqh);
    cudaGetSymbolAddress((void**)&wkh, g_wkh);
    cudaGetSymbolAddress((void**)&wvh, g_wvh);
    cudaGetSymbolAddress((void**)&qh, g_qh);   cudaGetSymbolAddress((void**)&ql, g_ql);
    cudaGetSymbolAddress((void**)&kh, g_kh);   cudaGetSymbolAddress((void**)&kl, g_kl);
    cudaGetSymbolAddress((void**)&vh, g_vh);   cudaGetSymbolAddress((void**)&vl, g_vl);
    cudaGetSymbolAddress((void**)&ph, g_ph);   cudaGetSymbolAddress((void**)&pl, g_pl);
    cudaGetSymbolAddress((void**)&sp, g_s);

    cudaFuncSetAttribute(hgemm<false, true>,  cudaFuncAttributeMaxDynamicSharedMemorySize, SMEM_TOTAL);
    cudaFuncSetAttribute(hgemm<true,  false>, cudaFuncAttributeMaxDynamicSharedMemorySize, SMEM_TOTAL);
    cudaFuncSetAttribute(hgemm<false, false>, cudaFuncAttributeMaxDynamicSharedMemorySize, SMEM_TOTAL);

    // 1) split fp32 inputs: x/ctx need hi+lo (A side), weights hi only (B side)
    splitk<<<(NQ  * DIMC / 4) / 256, 256>>>(x,   xh, xl, NQ  * DIMC / 4);
    splitk<<<(MKV * DIMC / 4) / 256, 256>>>(ctx, ch, cl, MKV * DIMC / 4);
    splitk_hi<<<(DIMC * DIMC / 4) / 256, 256>>>(Wq, wqh, DIMC * DIMC / 4);
    splitk_hi<<<(DIMC * DIMC / 4) / 256, 256>>>(Wk, wkh, DIMC * DIMC / 4);
    splitk_hi<<<(DIMC * DIMC / 4) / 256, 256>>>(Wv, wvh, DIMC * DIMC / 4);

    // 2) projections (NN): out = split(x@Wh + b); scale NOT folded (fp16 range)
    hgemm<false, true><<<dim3(DIMC/BN, NQ/BM),  256, SMEM_TOTAL>>>(
        xh, xl, wqh, DIMC, DIMC, DIMC, bq, 1.0f, nullptr, qh, ql, DIMC);
    hgemm<false, true><<<dim3(DIMC/BN, MKV/BM), 256, SMEM_TOTAL>>>(
        ch, cl, wkh, DIMC, DIMC, DIMC, bk, 1.0f, nullptr, kh, kl, DIMC);
    hgemm<false, true><<<dim3(DIMC/BN, MKV/BM), 256, SMEM_TOTAL>>>(
        ch, cl, wvh, DIMC, DIMC, DIMC, bv, 1.0f, nullptr, vh, vl, DIMC);

    // 3) scores S = (q @ k^T) / 32 (NT), fp32 out
    hgemm<true, false><<<dim3(MKV/BN, NQ/BM), 256, SMEM_TOTAL>>>(
        qh, ql, kh, DIMC, DIMC, DIMC, nullptr, 1.0f / 32.0f, sp, nullptr, nullptr, MKV);

    // 4) softmax rows -> split fp16 P (scaled x512)
    softmax_split<<<NQ, 256>>>(sp, ph, pl);

    // 5) O = (P_512 @ v) / 512 (NN), fp32 out
    hgemm<false, false><<<dim3(DIMC/BN, NQ/BM), 256, SMEM_TOTAL>>>(
        ph, pl, vh, MKV, DIMC, MKV, nullptr, 1.0f / 512.0f, out, nullptr, nullptr, DIMC);
}

// round 7
// speedup vs baseline: 7.1646x; 1.5117x over previous
#include <cuda_runtime.h>
#include <cuda_fp16.h>
#include <stdint.h>
#include <math.h>

constexpr int NQ   = 8192;
constexpr int MKV  = 8192;
constexpr int DIMC = 1024;

// ---------------- scratch (__device__ globals; allocation-free rule) --------
__device__ __half g_xh[(size_t)NQ*DIMC],  g_xl[(size_t)NQ*DIMC];
__device__ __half g_ch[(size_t)MKV*DIMC], g_cl[(size_t)MKV*DIMC];
__device__ __half g_wqh[(size_t)DIMC*DIMC];
__device__ __half g_wkh[(size_t)DIMC*DIMC];
__device__ __half g_wvh[(size_t)DIMC*DIMC];
__device__ __half g_qh[(size_t)NQ*DIMC];
__device__ __half g_kh[(size_t)MKV*DIMC];
__device__ __half g_vh[(size_t)MKV*DIMC];
__device__ float  g_s [(size_t)NQ*MKV];
__device__ __half g_ph[(size_t)NQ*MKV];

// ---------------- PTX helpers ----------------------------------------------
__device__ __forceinline__ uint32_t s2u(const void* p) {
    uint32_t a;
    asm("{ .reg .u64 t; cvta.to.shared.u64 t, %1; cvt.u32.u64 %0, t; }"
        : "=r"(a) : "l"(p));
    return a;
}
#define CPASYNC16(sa, gp) \
    asm volatile("cp.async.cg.shared.global [%0], [%1], 16;" :: "r"(sa), "l"(gp))
#define CPCOMMIT() asm volatile("cp.async.commit_group;")
#define CPWAIT(n)  asm volatile("cp.async.wait_group %0;" :: "n"(n))

#define LDSM_X4(r0,r1,r2,r3,a) \
    asm volatile("ldmatrix.sync.aligned.m8n8.x4.shared.b16 {%0,%1,%2,%3}, [%4];" \
        : "=r"(r0),"=r"(r1),"=r"(r2),"=r"(r3) : "r"(a))
#define LDSM_X4_T(r0,r1,r2,r3,a) \
    asm volatile("ldmatrix.sync.aligned.m8n8.x4.trans.shared.b16 {%0,%1,%2,%3}, [%4];" \
        : "=r"(r0),"=r"(r1),"=r"(r2),"=r"(r3) : "r"(a))

#define MMA16816(c0,c1,c2,c3,a0,a1,a2,a3,b0,b1) \
    asm volatile("mma.sync.aligned.m16n8k16.row.col.f32.f16.f16.f32 " \
        "{%0,%1,%2,%3}, {%4,%5,%6,%7}, {%8,%9}, {%0,%1,%2,%3};" \
        : "+f"(c0),"+f"(c1),"+f"(c2),"+f"(c3) \
        : "r"(a0),"r"(a1),"r"(a2),"r"(a3), "r"(b0),"r"(b1))

__device__ __forceinline__ void split2h(float a, float b, __half2& h, __half2& l) {
    __half ha = __float2half_rn(a);
    __half hb = __float2half_rn(b);
    h = __halves2half2(ha, hb);
    l = __halves2half2(__float2half_rn(a - __half2float(ha)),
                       __float2half_rn(b - __half2float(hb)));
}

// ---------------- split kernels (fp32 -> hi/lo fp16) ------------------------
__global__ __launch_bounds__(256)
void splitk(const float* __restrict__ in, __half* __restrict__ hi,
            __half* __restrict__ lo, int n4)
{
    int i = blockIdx.x * 256 + threadIdx.x;
    if (i >= n4) return;
    float4 v = ((const float4*)in)[i];
    __half2 h0, l0, h1, l1;
    split2h(v.x, v.y, h0, l0);
    split2h(v.z, v.w, h1, l1);
    ((__half2*)hi)[2*i]   = h0;
    ((__half2*)hi)[2*i+1] = h1;
    ((__half2*)lo)[2*i]   = l0;
    ((__half2*)lo)[2*i+1] = l1;
}

__global__ __launch_bounds__(256)
void splitk_hi(const float* __restrict__ in, __half* __restrict__ hi, int n4)
{
    int i = blockIdx.x * 256 + threadIdx.x;
    if (i >= n4) return;
    float4 v = ((const float4*)in)[i];
    ((__half2*)hi)[2*i]   = __halves2half2(__float2half_rn(v.x), __float2half_rn(v.y));
    ((__half2*)hi)[2*i+1] = __halves2half2(__float2half_rn(v.z), __float2half_rn(v.w));
}

// ---------------- fp16 GEMM, optional fused A-residual pass -----------------
// SPLIT_A: C = (Ahi + Alo) @ op(Bhi), else C = Ahi @ op(Bhi).
// A: [M,K] row-major fp16.  TRANS_B ? B:[N,K] : B:[K,N] row-major fp16.
// PROJ: Chi = fp16(acc + bias[col]);  else Cf = acc * alpha (fp32).
constexpr int BM = 128, BN = 128, BK = 64;
// per-stage smem (bytes): Ah@0  Al@16K  Bh@32K ; stage = 48KB
constexpr uint32_t OFF_AL = 16384, OFF_BH = 32768;
constexpr uint32_t STAGE  = 49152;
constexpr uint32_t SMEM_TOTAL = 2 * STAGE;   // 96 KB

template<bool TRANS_B, bool PROJ, bool SPLIT_A>
__global__ __launch_bounds__(256, 2)
void hgemm(const __half* __restrict__ Ahi, const __half* __restrict__ Alo,
           const __half* __restrict__ Bhi,
           int lda, int ldb, int K,
           const float* __restrict__ bias, float alpha,
           float* __restrict__ Cf, __half* __restrict__ Chi,
           int ldc)
{
    extern __shared__ char smem[];
    const uint32_t sS = s2u(smem);

    const int tid  = threadIdx.x;
    const int lane = tid & 31;
    const int wid  = tid >> 5;
    const int wm0  = (wid >> 2) * 64;
    const int wn0  = (wid & 3) * 32;
    const int m0   = blockIdx.y * BM;
    const int n0   = blockIdx.x * BN;

    // ---- global->smem loader geometry ----
    const int aRow0  = tid >> 3;
    const int aChunk = tid & 7;
    const uint32_t aSoff = (uint32_t)aRow0 * 128 + ((aChunk ^ (aRow0 & 7)) << 4);
    const int bRow0  = TRANS_B ? (tid >> 3) : (tid >> 4);
    const int bChunk = TRANS_B ? (tid & 7)  : (tid & 15);
    const uint32_t bSoff = TRANS_B
        ? ((uint32_t)bRow0 * 128 + ((bChunk ^ (bRow0 & 7)) << 4))
        : ((uint32_t)bRow0 * 256 + ((bChunk ^ (bRow0 & 7)) << 4));

    auto load_stage = [&](int stage, int k0) {
        const uint32_t sb = sS + (uint32_t)stage * STAGE;
        const __half* gAh = Ahi + (size_t)(m0 + aRow0) * lda + k0 + aChunk * 8;
        #pragma unroll
        for (int i = 0; i < 4; i++)
            CPASYNC16(sb + aSoff + i * 4096, gAh + (size_t)32 * i * lda);
        if (SPLIT_A) {
            const __half* gAl = Alo + (size_t)(m0 + aRow0) * lda + k0 + aChunk * 8;
            #pragma unroll
            for (int i = 0; i < 4; i++)
                CPASYNC16(sb + OFF_AL + aSoff + i * 4096, gAl + (size_t)32 * i * lda);
        }
        if (TRANS_B) {
            const __half* gBh = Bhi + (size_t)(n0 + bRow0) * ldb + k0 + bChunk * 8;
            #pragma unroll
            for (int i = 0; i < 4; i++)
                CPASYNC16(sb + OFF_BH + bSoff + i * 4096, gBh + (size_t)32 * i * ldb);
        } else {
            const __half* gBh = Bhi + (size_t)(k0 + bRow0) * ldb + n0 + bChunk * 8;
            #pragma unroll
            for (int i = 0; i < 4; i++)
                CPASYNC16(sb + OFF_BH + bSoff + i * 4096, gBh + (size_t)16 * i * ldb);
        }
    };

    // ---- mma fragment geometry (verified layout) ----
    const int sub  = lane >> 3;
    const int roct = lane & 7;

    int arow[4];
    #pragma unroll
    for (int mt = 0; mt < 4; mt++)
        arow[mt] = wm0 + mt * 16 + (sub & 1) * 8 + roct;

    int nrow[2];
    uint32_t bnnBase[2];
    #pragma unroll
    for (int np = 0; np < 2; np++) {
        nrow[np] = wn0 + np * 16 + (sub >> 1) * 8 + roct;
        int nch  = (wn0 >> 3) + np * 2 + (sub >> 1);
        bnnBase[np] = (uint32_t)(((sub & 1) * 8 + roct) * 256) + ((nch ^ roct) << 4);
    }

    float acc[4][4][4];
    #pragma unroll
    for (int mt = 0; mt < 4; mt++)
        #pragma unroll
        for (int nt = 0; nt < 4; nt++)
            #pragma unroll
            for (int e = 0; e < 4; e++)
                acc[mt][nt][e] = 0.0f;

    const int nkt = K >> 6;
    load_stage(0, 0);
    CPCOMMIT();

    for (int it = 0; it < nkt; ++it) {
        if (it + 1 < nkt) {
            load_stage((it + 1) & 1, (it + 1) * BK);
            CPCOMMIT();
            CPWAIT(1);
        } else {
            CPWAIT(0);
        }
        __syncthreads();

        const uint32_t sb     = sS + (uint32_t)(it & 1) * STAGE;
        const uint32_t aBaseH = sb;
        const uint32_t aBaseL = sb + OFF_AL;
        const uint32_t bBaseH = sb + OFF_BH;

        #pragma unroll
        for (int kk = 0; kk < 4; kk++) {
            uint32_t ah[4][4], al[4][4];
            #pragma unroll
            for (int mt = 0; mt < 4; mt++) {
                const int kch = kk * 2 + (sub >> 1);
                const uint32_t off = (uint32_t)arow[mt] * 128 + ((kch ^ (arow[mt] & 7)) << 4);
                LDSM_X4(ah[mt][0], ah[mt][1], ah[mt][2], ah[mt][3], aBaseH + off);
                if (SPLIT_A)
                    LDSM_X4(al[mt][0], al[mt][1], al[mt][2], al[mt][3], aBaseL + off);
            }
            uint32_t bh[2][4];
            #pragma unroll
            for (int np = 0; np < 2; np++) {
                if (TRANS_B) {
                    const int kch = kk * 2 + (sub & 1);
                    const uint32_t off = (uint32_t)nrow[np] * 128 + ((kch ^ (nrow[np] & 7)) << 4);
                    LDSM_X4(bh[np][0], bh[np][1], bh[np][2], bh[np][3], bBaseH + off);
                } else {
                    const uint32_t off = (uint32_t)kk * 4096 + bnnBase[np];
                    LDSM_X4_T(bh[np][0], bh[np][1], bh[np][2], bh[np][3], bBaseH + off);
                }
            }
            #pragma unroll
            for (int mt = 0; mt < 4; mt++) {
                #pragma unroll
                for (int nt = 0; nt < 4; nt++) {
                    uint32_t h0 = bh[nt >> 1][(nt & 1) * 2];
                    uint32_t h1 = bh[nt >> 1][(nt & 1) * 2 + 1];
                    MMA16816(acc[mt][nt][0], acc[mt][nt][1], acc[mt][nt][2], acc[mt][nt][3],
                             ah[mt][0], ah[mt][1], ah[mt][2], ah[mt][3], h0, h1);
                    if (SPLIT_A)
                        MMA16816(acc[mt][nt][0], acc[mt][nt][1], acc[mt][nt][2], acc[mt][nt][3],
                                 al[mt][0], al[mt][1], al[mt][2], al[mt][3], h0, h1);
                }
            }
        }
        __syncthreads();
    }

    // ---- epilogue ----
    const int g_  = lane >> 2;
    const int tig = lane & 3;
    #pragma unroll
    for (int nt = 0; nt < 4; nt++) {
        const int c = n0 + wn0 + nt * 8 + 2 * tig;
        float bv0 = 0.f, bv1 = 0.f;
        if (PROJ) { bv0 = bias[c]; bv1 = bias[c + 1]; }
        #pragma unroll
        for (int mt = 0; mt < 4; mt++) {
            const int r0 = m0 + wm0 + mt * 16 + g_;
            const int r1 = r0 + 8;
            if (PROJ) {
                *(__half2*)(Chi + (size_t)r0 * ldc + c) =
                    __halves2half2(__float2half_rn(acc[mt][nt][0] + bv0),
                                   __float2half_rn(acc[mt][nt][1] + bv1));
                *(__half2*)(Chi + (size_t)r1 * ldc + c) =
                    __halves2half2(__float2half_rn(acc[mt][nt][2] + bv0),
                                   __float2half_rn(acc[mt][nt][3] + bv1));
            } else {
                float2 o0 = { acc[mt][nt][0] * alpha, acc[mt][nt][1] * alpha };
                float2 o1 = { acc[mt][nt][2] * alpha, acc[mt][nt][3] * alpha };
                *(float2*)(Cf + (size_t)r0 * ldc + c) = o0;
                *(float2*)(Cf + (size_t)r1 * ldc + c) = o1;
            }
        }
    }
}

// ---------------- softmax: fp32 S row -> fp16 P (x512) ----------------------
__global__ __launch_bounds__(256)
void softmax_h(const float* __restrict__ S, __half* __restrict__ Ph)
{
    const int row  = blockIdx.x;
    const int tid  = threadIdx.x;
    const int lane = tid & 31;
    const int wrp  = tid >> 5;
    const float4* p4 = (const float4*)(S + (size_t)row * MKV);

    float4 v[8];
    float m = -3.0e38f;
    #pragma unroll
    for (int i = 0; i < 8; i++) {
        v[i] = p4[tid + i * 256];
        m = fmaxf(m, fmaxf(fmaxf(v[i].x, v[i].y), fmaxf(v[i].z, v[i].w)));
    }
    __shared__ float red[8];
    #pragma unroll
    for (int s = 16; s > 0; s >>= 1) m = fmaxf(m, __shfl_xor_sync(~0u, m, s));
    if (lane == 0) red[wrp] = m;
    __syncthreads();
    m = red[lane & 7];
    #pragma unroll
    for (int s = 4; s > 0; s >>= 1) m = fmaxf(m, __shfl_xor_sync(~0u, m, s));
    m = __shfl_sync(~0u, m, 0);

    float sum = 0.0f;
    #pragma unroll
    for (int i = 0; i < 8; i++) {
        v[i].x = __expf(v[i].x - m); v[i].y = __expf(v[i].y - m);
        v[i].z = __expf(v[i].z - m); v[i].w = __expf(v[i].w - m);
        sum += (v[i].x + v[i].y) + (v[i].z + v[i].w);
    }
    #pragma unroll
    for (int s = 16; s > 0; s >>= 1) sum += __shfl_xor_sync(~0u, sum, s);
    __syncthreads();
    if (lane == 0) red[wrp] = sum;
    __syncthreads();
    sum = red[lane & 7];
    #pragma unroll
    for (int s = 4; s > 0; s >>= 1) sum += __shfl_xor_sync(~0u, sum, s);
    sum = __shfl_sync(~0u, sum, 0);
    const float inv = 512.0f / sum;   // x512 keeps P out of fp16 subnormals

    __half2* h2 = (__half2*)(Ph + (size_t)row * MKV);
    #pragma unroll
    for (int i = 0; i < 8; i++) {
        const int idx = tid + i * 256;
        h2[idx*2]   = __halves2half2(__float2half_rn(v[i].x * inv),
                                     __float2half_rn(v[i].y * inv));
        h2[idx*2+1] = __halves2half2(__float2half_rn(v[i].z * inv),
                                     __float2half_rn(v[i].w * inv));
    }
}

// ---------------------------------------------------------------------------
extern "C" void kernel_launch(void* const* d_in, const int* in_sizes, int n_in,
                              void* d_out, int out_size)
{
    const float* x   = (const float*)d_in[0];
    const float* ctx = (const float*)d_in[1];
    const float* Wq  = (const float*)d_in[2];
    const float* bq  = (const float*)d_in[3];
    const float* Wk  = (const float*)d_in[4];
    const float* bk  = (const float*)d_in[5];
    const float* Wv  = (const float*)d_in[6];
    const float* bv  = (const float*)d_in[7];
    float* out = (float*)d_out;

    __half *xh,*xl,*ch,*cl,*wqh,*wkh,*wvh,*qh,*kh,*vh,*ph;
    float* sp;
    cudaGetSymbolAddress((void**)&xh, g_xh);   cudaGetSymbolAddress((void**)&xl, g_xl);
    cudaGetSymbolAddress((void**)&ch, g_ch);   cudaGetSymbolAddress((void**)&cl, g_cl);
    cudaGetSymbolAddress((void**)&wqh, g_wqh);
    cudaGetSymbolAddress((void**)&wkh, g_wkh);
    cudaGetSymbolAddress((void**)&wvh, g_wvh);
    cudaGetSymbolAddress((void**)&qh, g_qh);
    cudaGetSymbolAddress((void**)&kh, g_kh);
    cudaGetSymbolAddress((void**)&vh, g_vh);
    cudaGetSymbolAddress((void**)&ph, g_ph);
    cudaGetSymbolAddress((void**)&sp, g_s);

    cudaFuncSetAttribute(hgemm<false, true,  true >, cudaFuncAttributeMaxDynamicSharedMemorySize, SMEM_TOTAL);
    cudaFuncSetAttribute(hgemm<true,  false, false>, cudaFuncAttributeMaxDynamicSharedMemorySize, SMEM_TOTAL);
    cudaFuncSetAttribute(hgemm<false, false, false>, cudaFuncAttributeMaxDynamicSharedMemorySize, SMEM_TOTAL);

    // 1) split fp32 inputs: x/ctx hi+lo (A side of projections), weights hi
    splitk<<<(NQ  * DIMC / 4) / 256, 256>>>(x,   xh, xl, NQ  * DIMC / 4);
    splitk<<<(MKV * DIMC / 4) / 256, 256>>>(ctx, ch, cl, MKV * DIMC / 4);
    splitk_hi<<<(DIMC * DIMC / 4) / 256, 256>>>(Wq, wqh, DIMC * DIMC / 4);
    splitk_hi<<<(DIMC * DIMC / 4) / 256, 256>>>(Wk, wkh, DIMC * DIMC / 4);
    splitk_hi<<<(DIMC * DIMC / 4) / 256, 256>>>(Wv, wvh, DIMC * DIMC / 4);

    // 2) projections (NN, 2-pass A): out = fp16(x@Wh + b)
    hgemm<false, true, true><<<dim3(DIMC/BN, NQ/BM),  256, SMEM_TOTAL>>>(
        xh, xl, wqh, DIMC, DIMC, DIMC, bq, 1.0f, nullptr, qh, DIMC);
    hgemm<false, true, true><<<dim3(DIMC/BN, MKV/BM), 256, SMEM_TOTAL>>>(
        ch, cl, wkh, DIMC, DIMC, DIMC, bk, 1.0f, nullptr, kh, DIMC);
    hgemm<false, true, true><<<dim3(DIMC/BN, MKV/BM), 256, SMEM_TOTAL>>>(
        ch, cl, wvh, DIMC, DIMC, DIMC, bv, 1.0f, nullptr, vh, DIMC);

    // 3) scores S = (q @ k^T) / 32 (NT, single-pass), fp32 out
    hgemm<true, false, false><<<dim3(MKV/BN, NQ/BM), 256, SMEM_TOTAL>>>(
        qh, nullptr, kh, DIMC, DIMC, DIMC, nullptr, 1.0f / 32.0f, sp, nullptr, MKV);

    // 4) softmax rows -> fp16 P (scaled x512)
    softmax_h<<<NQ, 256>>>(sp, ph);

    // 5) O = (P_512 @ v) / 512 (NN, single-pass), fp32 out
    hgemm<false, false, false><<<dim3(DIMC/BN, NQ/BM), 256, SMEM_TOTAL>>>(
        ph, nullptr, vh, MKV, DIMC, MKV, nullptr, 1.0f / 512.0f, out, nullptr, DIMC);
}

// round 8
// speedup vs baseline: 8.0074x; 1.1176x over previous
#include <cuda_runtime.h>
#include <cuda_fp16.h>
#include <stdint.h>
#include <math.h>

constexpr int NQ   = 8192;
constexpr int MKV  = 8192;
constexpr int DIMC = 1024;

// ---------------- scratch (__device__ globals; allocation-free rule) --------
__device__ __half g_xh[(size_t)NQ*DIMC];
__device__ __half g_ch[(size_t)MKV*DIMC];
__device__ __half g_wqh[(size_t)DIMC*DIMC];
__device__ __half g_wkh[(size_t)DIMC*DIMC];
__device__ __half g_wvh[(size_t)DIMC*DIMC];
__device__ __half g_qh[(size_t)NQ*DIMC];
__device__ __half g_kh[(size_t)MKV*DIMC];
__device__ __half g_vh[(size_t)MKV*DIMC];
__device__ float  g_s [(size_t)NQ*MKV];
__device__ __half g_ph[(size_t)NQ*MKV];

// ---------------- PTX helpers ----------------------------------------------
__device__ __forceinline__ uint32_t s2u(const void* p) {
    uint32_t a;
    asm("{ .reg .u64 t; cvta.to.shared.u64 t, %1; cvt.u32.u64 %0, t; }"
        : "=r"(a) : "l"(p));
    return a;
}
#define CPASYNC16(sa, gp) \
    asm volatile("cp.async.cg.shared.global [%0], [%1], 16;" :: "r"(sa), "l"(gp))
#define CPCOMMIT() asm volatile("cp.async.commit_group;")
#define CPWAIT(n)  asm volatile("cp.async.wait_group %0;" :: "n"(n))

#define LDSM_X4(r0,r1,r2,r3,a) \
    asm volatile("ldmatrix.sync.aligned.m8n8.x4.shared.b16 {%0,%1,%2,%3}, [%4];" \
        : "=r"(r0),"=r"(r1),"=r"(r2),"=r"(r3) : "r"(a))
#define LDSM_X4_T(r0,r1,r2,r3,a) \
    asm volatile("ldmatrix.sync.aligned.m8n8.x4.trans.shared.b16 {%0,%1,%2,%3}, [%4];" \
        : "=r"(r0),"=r"(r1),"=r"(r2),"=r"(r3) : "r"(a))

#define MMA16816(c0,c1,c2,c3,a0,a1,a2,a3,b0,b1) \
    asm volatile("mma.sync.aligned.m16n8k16.row.col.f32.f16.f16.f32 " \
        "{%0,%1,%2,%3}, {%4,%5,%6,%7}, {%8,%9}, {%0,%1,%2,%3};" \
        : "+f"(c0),"+f"(c1),"+f"(c2),"+f"(c3) \
        : "r"(a0),"r"(a1),"r"(a2),"r"(a3), "r"(b0),"r"(b1))

// ---------------- fp32 -> fp16 conversion -----------------------------------
__global__ __launch_bounds__(256)
void tohalf(const float* __restrict__ in, __half* __restrict__ hi, int n4)
{
    int i = blockIdx.x * 256 + threadIdx.x;
    if (i >= n4) return;
    float4 v = ((const float4*)in)[i];
    ((__half2*)hi)[2*i]   = __halves2half2(__float2half_rn(v.x), __float2half_rn(v.y));
    ((__half2*)hi)[2*i+1] = __halves2half2(__float2half_rn(v.z), __float2half_rn(v.w));
}

// ---------------- single-pass fp16 GEMM, fp32 accumulate --------------------
// C = A @ op(B).  A: [M,K] row-major fp16.
// TRANS_B ? B:[N,K] : B:[K,N] row-major fp16.
// PROJ: Chi = fp16(acc + bias[col]);  else Cf = acc * alpha (fp32).
constexpr int BM = 128, BN = 128, BK = 64;
// per-stage smem (bytes): A@0  B@16K ; stage = 32KB
constexpr uint32_t OFF_B = 16384;
constexpr uint32_t STAGE = 32768;
constexpr uint32_t SMEM_TOTAL = 2 * STAGE;   // 64 KB

template<bool TRANS_B, bool PROJ>
__global__ __launch_bounds__(256, 2)
void hgemm(const __half* __restrict__ A, const __half* __restrict__ B,
           int lda, int ldb, int K,
           const float* __restrict__ bias, float alpha,
           float* __restrict__ Cf, __half* __restrict__ Chi,
           int ldc)
{
    extern __shared__ char smem[];
    const uint32_t sS = s2u(smem);

    const int tid  = threadIdx.x;
    const int lane = tid & 31;
    const int wid  = tid >> 5;
    const int wm0  = (wid >> 2) * 64;
    const int wn0  = (wid & 3) * 32;
    const int m0   = blockIdx.y * BM;
    const int n0   = blockIdx.x * BN;

    // ---- global->smem loader geometry ----
    const int aRow0  = tid >> 3;
    const int aChunk = tid & 7;
    const uint32_t aSoff = (uint32_t)aRow0 * 128 + ((aChunk ^ (aRow0 & 7)) << 4);
    const int bRow0  = TRANS_B ? (tid >> 3) : (tid >> 4);
    const int bChunk = TRANS_B ? (tid & 7)  : (tid & 15);
    const uint32_t bSoff = TRANS_B
        ? ((uint32_t)bRow0 * 128 + ((bChunk ^ (bRow0 & 7)) << 4))
        : ((uint32_t)bRow0 * 256 + ((bChunk ^ (bRow0 & 7)) << 4));

    auto load_stage = [&](int stage, int k0) {
        const uint32_t sb = sS + (uint32_t)stage * STAGE;
        const __half* gA = A + (size_t)(m0 + aRow0) * lda + k0 + aChunk * 8;
        #pragma unroll
        for (int i = 0; i < 4; i++)
            CPASYNC16(sb + aSoff + i * 4096, gA + (size_t)32 * i * lda);
        if (TRANS_B) {
            const __half* gB = B + (size_t)(n0 + bRow0) * ldb + k0 + bChunk * 8;
            #pragma unroll
            for (int i = 0; i < 4; i++)
                CPASYNC16(sb + OFF_B + bSoff + i * 4096, gB + (size_t)32 * i * ldb);
        } else {
            const __half* gB = B + (size_t)(k0 + bRow0) * ldb + n0 + bChunk * 8;
            #pragma unroll
            for (int i = 0; i < 4; i++)
                CPASYNC16(sb + OFF_B + bSoff + i * 4096, gB + (size_t)16 * i * ldb);
        }
    };

    // ---- mma fragment geometry (verified layout) ----
    const int sub  = lane >> 3;
    const int roct = lane & 7;

    int arow[4];
    #pragma unroll
    for (int mt = 0; mt < 4; mt++)
        arow[mt] = wm0 + mt * 16 + (sub & 1) * 8 + roct;

    int nrow[2];
    uint32_t bnnBase[2];
    #pragma unroll
    for (int np = 0; np < 2; np++) {
        nrow[np] = wn0 + np * 16 + (sub >> 1) * 8 + roct;
        int nch  = (wn0 >> 3) + np * 2 + (sub >> 1);
        bnnBase[np] = (uint32_t)(((sub & 1) * 8 + roct) * 256) + ((nch ^ roct) << 4);
    }

    float acc[4][4][4];
    #pragma unroll
    for (int mt = 0; mt < 4; mt++)
        #pragma unroll
        for (int nt = 0; nt < 4; nt++)
            #pragma unroll
            for (int e = 0; e < 4; e++)
                acc[mt][nt][e] = 0.0f;

    const int nkt = K >> 6;
    load_stage(0, 0);
    CPCOMMIT();

    for (int it = 0; it < nkt; ++it) {
        if (it + 1 < nkt) {
            load_stage((it + 1) & 1, (it + 1) * BK);
            CPCOMMIT();
            CPWAIT(1);
        } else {
            CPWAIT(0);
        }
        __syncthreads();

        const uint32_t sb    = sS + (uint32_t)(it & 1) * STAGE;
        const uint32_t aBase = sb;
        const uint32_t bBase = sb + OFF_B;

        #pragma unroll
        for (int kk = 0; kk < 4; kk++) {
            uint32_t af[4][4];
            #pragma unroll
            for (int mt = 0; mt < 4; mt++) {
                const int kch = kk * 2 + (sub >> 1);
                const uint32_t off = (uint32_t)arow[mt] * 128 + ((kch ^ (arow[mt] & 7)) << 4);
                LDSM_X4(af[mt][0], af[mt][1], af[mt][2], af[mt][3], aBase + off);
            }
            uint32_t bf[2][4];
            #pragma unroll
            for (int np = 0; np < 2; np++) {
                if (TRANS_B) {
                    const int kch = kk * 2 + (sub & 1);
                    const uint32_t off = (uint32_t)nrow[np] * 128 + ((kch ^ (nrow[np] & 7)) << 4);
                    LDSM_X4(bf[np][0], bf[np][1], bf[np][2], bf[np][3], bBase + off);
                } else {
                    const uint32_t off = (uint32_t)kk * 4096 + bnnBase[np];
                    LDSM_X4_T(bf[np][0], bf[np][1], bf[np][2], bf[np][3], bBase + off);
                }
            }
            #pragma unroll
            for (int mt = 0; mt < 4; mt++) {
                #pragma unroll
                for (int nt = 0; nt < 4; nt++) {
                    uint32_t b0 = bf[nt >> 1][(nt & 1) * 2];
                    uint32_t b1 = bf[nt >> 1][(nt & 1) * 2 + 1];
                    MMA16816(acc[mt][nt][0], acc[mt][nt][1], acc[mt][nt][2], acc[mt][nt][3],
                             af[mt][0], af[mt][1], af[mt][2], af[mt][3], b0, b1);
                }
            }
        }
        __syncthreads();
    }

    // ---- epilogue ----
    const int g_  = lane >> 2;
    const int tig = lane & 3;
    #pragma unroll
    for (int nt = 0; nt < 4; nt++) {
        const int c = n0 + wn0 + nt * 8 + 2 * tig;
        float bv0 = 0.f, bv1 = 0.f;
        if (PROJ) { bv0 = bias[c]; bv1 = bias[c + 1]; }
        #pragma unroll
        for (int mt = 0; mt < 4; mt++) {
            const int r0 = m0 + wm0 + mt * 16 + g_;
            const int r1 = r0 + 8;
            if (PROJ) {
                *(__half2*)(Chi + (size_t)r0 * ldc + c) =
                    __halves2half2(__float2half_rn(acc[mt][nt][0] + bv0),
                                   __float2half_rn(acc[mt][nt][1] + bv1));
                *(__half2*)(Chi + (size_t)r1 * ldc + c) =
                    __halves2half2(__float2half_rn(acc[mt][nt][2] + bv0),
                                   __float2half_rn(acc[mt][nt][3] + bv1));
            } else {
                float2 o0 = { acc[mt][nt][0] * alpha, acc[mt][nt][1] * alpha };
                float2 o1 = { acc[mt][nt][2] * alpha, acc[mt][nt][3] * alpha };
                *(float2*)(Cf + (size_t)r0 * ldc + c) = o0;
                *(float2*)(Cf + (size_t)r1 * ldc + c) = o1;
            }
        }
    }
}

// ---------------- softmax: fp32 S row -> fp16 P (x512) ----------------------
__global__ __launch_bounds__(256)
void softmax_h(const float* __restrict__ S, __half* __restrict__ Ph)
{
    const int row  = blockIdx.x;
    const int tid  = threadIdx.x;
    const int lane = tid & 31;
    const int wrp  = tid >> 5;
    const float4* p4 = (const float4*)(S + (size_t)row * MKV);

    float4 v[8];
    float m = -3.0e38f;
    #pragma unroll
    for (int i = 0; i < 8; i++) {
        v[i] = p4[tid + i * 256];
        m = fmaxf(m, fmaxf(fmaxf(v[i].x, v[i].y), fmaxf(v[i].z, v[i].w)));
    }
    __shared__ float red[8];
    #pragma unroll
    for (int s = 16; s > 0; s >>= 1) m = fmaxf(m, __shfl_xor_sync(~0u, m, s));
    if (lane == 0) red[wrp] = m;
    __syncthreads();
    m = red[lane & 7];
    #pragma unroll
    for (int s = 4; s > 0; s >>= 1) m = fmaxf(m, __shfl_xor_sync(~0u, m, s));
    m = __shfl_sync(~0u, m, 0);

    float sum = 0.0f;
    #pragma unroll
    for (int i = 0; i < 8; i++) {
        v[i].x = __expf(v[i].x - m); v[i].y = __expf(v[i].y - m);
        v[i].z = __expf(v[i].z - m); v[i].w = __expf(v[i].w - m);
        sum += (v[i].x + v[i].y) + (v[i].z + v[i].w);
    }
    #pragma unroll
    for (int s = 16; s > 0; s >>= 1) sum += __shfl_xor_sync(~0u, sum, s);
    __syncthreads();
    if (lane == 0) red[wrp] = sum;
    __syncthreads();
    sum = red[lane & 7];
    #pragma unroll
    for (int s = 4; s > 0; s >>= 1) sum += __shfl_xor_sync(~0u, sum, s);
    sum = __shfl_sync(~0u, sum, 0);
    const float inv = 512.0f / sum;   // x512 keeps P out of fp16 subnormals

    __half2* h2 = (__half2*)(Ph + (size_t)row * MKV);
    #pragma unroll
    for (int i = 0; i < 8; i++) {
        const int idx = tid + i * 256;
        h2[idx*2]   = __halves2half2(__float2half_rn(v[i].x * inv),
                                     __float2half_rn(v[i].y * inv));
        h2[idx*2+1] = __halves2half2(__float2half_rn(v[i].z * inv),
                                     __float2half_rn(v[i].w * inv));
    }
}

// ---------------------------------------------------------------------------
extern "C" void kernel_launch(void* const* d_in, const int* in_sizes, int n_in,
                              void* d_out, int out_size)
{
    const float* x   = (const float*)d_in[0];
    const float* ctx = (const float*)d_in[1];
    const float* Wq  = (const float*)d_in[2];
    const float* bq  = (const float*)d_in[3];
    const float* Wk  = (const float*)d_in[4];
    const float* bk  = (const float*)d_in[5];
    const float* Wv  = (const float*)d_in[6];
    const float* bv  = (const float*)d_in[7];
    float* out = (float*)d_out;

    __half *xh,*ch,*wqh,*wkh,*wvh,*qh,*kh,*vh,*ph;
    float* sp;
    cudaGetSymbolAddress((void**)&xh, g_xh);
    cudaGetSymbolAddress((void**)&ch, g_ch);
    cudaGetSymbolAddress((void**)&wqh, g_wqh);
    cudaGetSymbolAddress((void**)&wkh, g_wkh);
    cudaGetSymbolAddress((void**)&wvh, g_wvh);
    cudaGetSymbolAddress((void**)&qh, g_qh);
    cudaGetSymbolAddress((void**)&kh, g_kh);
    cudaGetSymbolAddress((void**)&vh, g_vh);
    cudaGetSymbolAddress((void**)&ph, g_ph);
    cudaGetSymbolAddress((void**)&sp, g_s);

    cudaFuncSetAttribute(hgemm<false, true >, cudaFuncAttributeMaxDynamicSharedMemorySize, SMEM_TOTAL);
    cudaFuncSetAttribute(hgemm<true,  false>, cudaFuncAttributeMaxDynamicSharedMemorySize, SMEM_TOTAL);
    cudaFuncSetAttribute(hgemm<false, false>, cudaFuncAttributeMaxDynamicSharedMemorySize, SMEM_TOTAL);

    // 1) convert fp32 inputs to fp16
    tohalf<<<(NQ  * DIMC / 4) / 256, 256>>>(x,   xh, NQ  * DIMC / 4);
    tohalf<<<(MKV * DIMC / 4) / 256, 256>>>(ctx, ch, MKV * DIMC / 4);
    tohalf<<<(DIMC * DIMC / 4) / 256, 256>>>(Wq, wqh, DIMC * DIMC / 4);
    tohalf<<<(DIMC * DIMC / 4) / 256, 256>>>(Wk, wkh, DIMC * DIMC / 4);
    tohalf<<<(DIMC * DIMC / 4) / 256, 256>>>(Wv, wvh, DIMC * DIMC / 4);

    // 2) projections (NN, single-pass): out = fp16(x@W + b)
    hgemm<false, true><<<dim3(DIMC/BN, NQ/BM),  256, SMEM_TOTAL>>>(
        xh, wqh, DIMC, DIMC, DIMC, bq, 1.0f, nullptr, qh, DIMC);
    hgemm<false, true><<<dim3(DIMC/BN, MKV/BM), 256, SMEM_TOTAL>>>(
        ch, wkh, DIMC, DIMC, DIMC, bk, 1.0f, nullptr, kh, DIMC);
    hgemm<false, true><<<dim3(DIMC/BN, MKV/BM), 256, SMEM_TOTAL>>>(
        ch, wvh, DIMC, DIMC, DIMC, bv, 1.0f, nullptr, vh, DIMC);

    // 3) scores S = (q @ k^T) / 32 (NT), fp32 out
    hgemm<true, false><<<dim3(MKV/BN, NQ/BM), 256, SMEM_TOTAL>>>(
        qh, kh, DIMC, DIMC, DIMC, nullptr, 1.0f / 32.0f, sp, nullptr, MKV);

    // 4) softmax rows -> fp16 P (scaled x512)
    softmax_h<<<NQ, 256>>>(sp, ph);

    // 5) O = (P_512 @ v) / 512 (NN), fp32 out
    hgemm<false, false><<<dim3(DIMC/BN, NQ/BM), 256, SMEM_TOTAL>>>(
        ph, vh, MKV, DIMC, MKV, nullptr, 1.0f / 512.0f, out, nullptr, DIMC);
}

// round 9
// speedup vs baseline: 8.5106x; 1.0628x over previous
#include <cuda_runtime.h>
#include <cuda_fp16.h>
#include <stdint.h>
#include <math.h>

constexpr int NQ   = 8192;
constexpr int MKV  = 8192;
constexpr int DIMC = 1024;

// ---------------- scratch (__device__ globals; allocation-free rule) --------
__device__ __half g_xh[(size_t)NQ*DIMC];
__device__ __half g_ch[(size_t)MKV*DIMC];
__device__ __half g_wqh[(size_t)DIMC*DIMC];
__device__ __half g_wkh[(size_t)DIMC*DIMC];
__device__ __half g_wvh[(size_t)DIMC*DIMC];
__device__ __half g_qh[(size_t)NQ*DIMC];
__device__ __half g_kh[(size_t)MKV*DIMC];
__device__ __half g_vh[(size_t)MKV*DIMC];
__device__ __half g_s [(size_t)NQ*MKV];    // fp16 scores
__device__ __half g_ph[(size_t)NQ*MKV];    // fp16 probs (x512)

// ---------------- PTX helpers ----------------------------------------------
__device__ __forceinline__ uint32_t s2u(const void* p) {
    uint32_t a;
    asm("{ .reg .u64 t; cvta.to.shared.u64 t, %1; cvt.u32.u64 %0, t; }"
        : "=r"(a) : "l"(p));
    return a;
}
#define CPASYNC16(sa, gp) \
    asm volatile("cp.async.cg.shared.global [%0], [%1], 16;" :: "r"(sa), "l"(gp))
#define CPCOMMIT() asm volatile("cp.async.commit_group;")
#define CPWAIT(n)  asm volatile("cp.async.wait_group %0;" :: "n"(n))

#define LDSM_X4(r0,r1,r2,r3,a) \
    asm volatile("ldmatrix.sync.aligned.m8n8.x4.shared.b16 {%0,%1,%2,%3}, [%4];" \
        : "=r"(r0),"=r"(r1),"=r"(r2),"=r"(r3) : "r"(a))
#define LDSM_X4_T(r0,r1,r2,r3,a) \
    asm volatile("ldmatrix.sync.aligned.m8n8.x4.trans.shared.b16 {%0,%1,%2,%3}, [%4];" \
        : "=r"(r0),"=r"(r1),"=r"(r2),"=r"(r3) : "r"(a))

#define MMA16816(c0,c1,c2,c3,a0,a1,a2,a3,b0,b1) \
    asm volatile("mma.sync.aligned.m16n8k16.row.col.f32.f16.f16.f32 " \
        "{%0,%1,%2,%3}, {%4,%5,%6,%7}, {%8,%9}, {%0,%1,%2,%3};" \
        : "+f"(c0),"+f"(c1),"+f"(c2),"+f"(c3) \
        : "r"(a0),"r"(a1),"r"(a2),"r"(a3), "r"(b0),"r"(b1))

// ---------------- fp32 -> fp16 conversion -----------------------------------
__global__ __launch_bounds__(256)
void tohalf(const float* __restrict__ in, __half* __restrict__ hi, int n4)
{
    int i = blockIdx.x * 256 + threadIdx.x;
    if (i >= n4) return;
    float4 v = ((const float4*)in)[i];
    ((__half2*)hi)[2*i]   = __halves2half2(__float2half_rn(v.x), __float2half_rn(v.y));
    ((__half2*)hi)[2*i+1] = __halves2half2(__float2half_rn(v.z), __float2half_rn(v.w));
}

// ---------------- single-pass fp16 GEMM, fp32 acc, 3-stage pipeline ---------
// C = A @ op(B).  A: [M,K] row-major fp16.
// TRANS_B ? B:[N,K] : B:[K,N] row-major fp16.
// MODE 0: Cf  = acc * alpha                (fp32 out)
// MODE 1: Chi = fp16(acc + bias[col])      (projection)
// MODE 2: Chi = fp16(acc * alpha)          (fp16 scaled out, e.g. scores)
constexpr int BM = 128, BN = 128, BK = 64;
constexpr uint32_t OFF_B = 16384;            // per-stage: A@0 B@16K
constexpr uint32_t STAGE = 32768;            // 32 KB
constexpr int      NSTG  = 3;
constexpr uint32_t SMEM_TOTAL = NSTG * STAGE;   // 96 KB

template<bool TRANS_B, int MODE>
__global__ __launch_bounds__(256, 2)
void hgemm(const __half* __restrict__ A, const __half* __restrict__ B,
           int lda, int ldb, int K,
           const float* __restrict__ bias, float alpha,
           float* __restrict__ Cf, __half* __restrict__ Chi,
           int ldc)
{
    extern __shared__ char smem[];
    const uint32_t sS = s2u(smem);

    const int tid  = threadIdx.x;
    const int lane = tid & 31;
    const int wid  = tid >> 5;
    const int wm0  = (wid >> 2) * 64;
    const int wn0  = (wid & 3) * 32;
    const int m0   = blockIdx.y * BM;
    const int n0   = blockIdx.x * BN;

    // ---- global->smem loader geometry ----
    const int aRow0  = tid >> 3;
    const int aChunk = tid & 7;
    const uint32_t aSoff = (uint32_t)aRow0 * 128 + ((aChunk ^ (aRow0 & 7)) << 4);
    const int bRow0  = TRANS_B ? (tid >> 3) : (tid >> 4);
    const int bChunk = TRANS_B ? (tid & 7)  : (tid & 15);
    const uint32_t bSoff = TRANS_B
        ? ((uint32_t)bRow0 * 128 + ((bChunk ^ (bRow0 & 7)) << 4))
        : ((uint32_t)bRow0 * 256 + ((bChunk ^ (bRow0 & 7)) << 4));

    auto load_stage = [&](int stage, int k0) {
        const uint32_t sb = sS + (uint32_t)stage * STAGE;
        const __half* gA = A + (size_t)(m0 + aRow0) * lda + k0 + aChunk * 8;
        #pragma unroll
        for (int i = 0; i < 4; i++)
            CPASYNC16(sb + aSoff + i * 4096, gA + (size_t)32 * i * lda);
        if (TRANS_B) {
            const __half* gB = B + (size_t)(n0 + bRow0) * ldb + k0 + bChunk * 8;
            #pragma unroll
            for (int i = 0; i < 4; i++)
                CPASYNC16(sb + OFF_B + bSoff + i * 4096, gB + (size_t)32 * i * ldb);
        } else {
            const __half* gB = B + (size_t)(k0 + bRow0) * ldb + n0 + bChunk * 8;
            #pragma unroll
            for (int i = 0; i < 4; i++)
                CPASYNC16(sb + OFF_B + bSoff + i * 4096, gB + (size_t)16 * i * ldb);
        }
    };

    // ---- mma fragment geometry (verified layout) ----
    const int sub  = lane >> 3;
    const int roct = lane & 7;

    int arow[4];
    #pragma unroll
    for (int mt = 0; mt < 4; mt++)
        arow[mt] = wm0 + mt * 16 + (sub & 1) * 8 + roct;

    int nrow[2];
    uint32_t bnnBase[2];
    #pragma unroll
    for (int np = 0; np < 2; np++) {
        nrow[np] = wn0 + np * 16 + (sub >> 1) * 8 + roct;
        int nch  = (wn0 >> 3) + np * 2 + (sub >> 1);
        bnnBase[np] = (uint32_t)(((sub & 1) * 8 + roct) * 256) + ((nch ^ roct) << 4);
    }

    float acc[4][4][4];
    #pragma unroll
    for (int mt = 0; mt < 4; mt++)
        #pragma unroll
        for (int nt = 0; nt < 4; nt++)
            #pragma unroll
            for (int e = 0; e < 4; e++)
                acc[mt][nt][e] = 0.0f;

    const int nkt = K >> 6;
    load_stage(0, 0);   CPCOMMIT();
    load_stage(1, BK);  CPCOMMIT();

    int buf = 0, pf = 2;                       // compute buffer / next prefetch buffer
    for (int it = 0; it < nkt; ++it) {
        if (it + 1 < nkt) CPWAIT(1); else CPWAIT(0);
        __syncthreads();                       // data(it) visible + all warps done with buf(it-1)

        if (it + 2 < nkt) {
            load_stage(pf, (it + 2) * BK);     // buf(it-1)'s slot — safe after the sync
            CPCOMMIT();
        }

        const uint32_t sb    = sS + (uint32_t)buf * STAGE;
        const uint32_t aBase = sb;
        const uint32_t bBase = sb + OFF_B;

        #pragma unroll
        for (int kk = 0; kk < 4; kk++) {
            uint32_t af[4][4];
            #pragma unroll
            for (int mt = 0; mt < 4; mt++) {
                const int kch = kk * 2 + (sub >> 1);
                const uint32_t off = (uint32_t)arow[mt] * 128 + ((kch ^ (arow[mt] & 7)) << 4);
                LDSM_X4(af[mt][0], af[mt][1], af[mt][2], af[mt][3], aBase + off);
            }
            uint32_t bf[2][4];
            #pragma unroll
            for (int np = 0; np < 2; np++) {
                if (TRANS_B) {
                    const int kch = kk * 2 + (sub & 1);
                    const uint32_t off = (uint32_t)nrow[np] * 128 + ((kch ^ (nrow[np] & 7)) << 4);
                    LDSM_X4(bf[np][0], bf[np][1], bf[np][2], bf[np][3], bBase + off);
                } else {
                    const uint32_t off = (uint32_t)kk * 4096 + bnnBase[np];
                    LDSM_X4_T(bf[np][0], bf[np][1], bf[np][2], bf[np][3], bBase + off);
                }
            }
            #pragma unroll
            for (int mt = 0; mt < 4; mt++) {
                #pragma unroll
                for (int nt = 0; nt < 4; nt++) {
                    uint32_t b0 = bf[nt >> 1][(nt & 1) * 2];
                    uint32_t b1 = bf[nt >> 1][(nt & 1) * 2 + 1];
                    MMA16816(acc[mt][nt][0], acc[mt][nt][1], acc[mt][nt][2], acc[mt][nt][3],
                             af[mt][0], af[mt][1], af[mt][2], af[mt][3], b0, b1);
                }
            }
        }
        buf = (buf + 1 == NSTG) ? 0 : buf + 1;
        pf  = (pf  + 1 == NSTG) ? 0 : pf  + 1;
    }

    // ---- epilogue ----
    const int g_  = lane >> 2;
    const int tig = lane & 3;
    #pragma unroll
    for (int nt = 0; nt < 4; nt++) {
        const int c = n0 + wn0 + nt * 8 + 2 * tig;
        float bv0 = 0.f, bv1 = 0.f;
        if (MODE == 1) { bv0 = bias[c]; bv1 = bias[c + 1]; }
        #pragma unroll
        for (int mt = 0; mt < 4; mt++) {
            const int r0 = m0 + wm0 + mt * 16 + g_;
            const int r1 = r0 + 8;
            if (MODE == 1) {
                *(__half2*)(Chi + (size_t)r0 * ldc + c) =
                    __halves2half2(__float2half_rn(acc[mt][nt][0] + bv0),
                                   __float2half_rn(acc[mt][nt][1] + bv1));
                *(__half2*)(Chi + (size_t)r1 * ldc + c) =
                    __halves2half2(__float2half_rn(acc[mt][nt][2] + bv0),
                                   __float2half_rn(acc[mt][nt][3] + bv1));
            } else if (MODE == 2) {
                *(__half2*)(Chi + (size_t)r0 * ldc + c) =
                    __halves2half2(__float2half_rn(acc[mt][nt][0] * alpha),
                                   __float2half_rn(acc[mt][nt][1] * alpha));
                *(__half2*)(Chi + (size_t)r1 * ldc + c) =
                    __halves2half2(__float2half_rn(acc[mt][nt][2] * alpha),
                                   __float2half_rn(acc[mt][nt][3] * alpha));
            } else {
                float2 o0 = { acc[mt][nt][0] * alpha, acc[mt][nt][1] * alpha };
                float2 o1 = { acc[mt][nt][2] * alpha, acc[mt][nt][3] * alpha };
                *(float2*)(Cf + (size_t)r0 * ldc + c) = o0;
                *(float2*)(Cf + (size_t)r1 * ldc + c) = o1;
            }
        }
    }
}

// ---------------- softmax: fp16 S row -> fp16 P (x512) ----------------------
__global__ __launch_bounds__(256)
void softmax_h(const __half* __restrict__ S, __half* __restrict__ Ph)
{
    const int row  = blockIdx.x;
    const int tid  = threadIdx.x;
    const int lane = tid & 31;
    const int wrp  = tid >> 5;
    const uint4* p4 = (const uint4*)(S + (size_t)row * MKV);   // 1024 uint4/row

    float v[32];
    float m = -3.0e38f;
    #pragma unroll
    for (int i = 0; i < 4; i++) {
        uint4 u = p4[tid + i * 256];
        const uint32_t w[4] = { u.x, u.y, u.z, u.w };
        #pragma unroll
        for (int j = 0; j < 4; j++) {
            float2 f = __half22float2(*(const __half2*)&w[j]);
            v[i*8 + j*2]     = f.x;
            v[i*8 + j*2 + 1] = f.y;
            m = fmaxf(m, fmaxf(f.x, f.y));
        }
    }

    __shared__ float red[8];
    #pragma unroll
    for (int s = 16; s > 0; s >>= 1) m = fmaxf(m, __shfl_xor_sync(~0u, m, s));
    if (lane == 0) red[wrp] = m;
    __syncthreads();
    m = red[lane & 7];
    #pragma unroll
    for (int s = 4; s > 0; s >>= 1) m = fmaxf(m, __shfl_xor_sync(~0u, m, s));
    m = __shfl_sync(~0u, m, 0);

    float sum = 0.0f;
    #pragma unroll
    for (int i = 0; i < 32; i++) {
        v[i] = __expf(v[i] - m);
        sum += v[i];
    }
    #pragma unroll
    for (int s = 16; s > 0; s >>= 1) sum += __shfl_xor_sync(~0u, sum, s);
    __syncthreads();
    if (lane == 0) red[wrp] = sum;
    __syncthreads();
    sum = red[lane & 7];
    #pragma unroll
    for (int s = 4; s > 0; s >>= 1) sum += __shfl_xor_sync(~0u, sum, s);
    sum = __shfl_sync(~0u, sum, 0);
    const float inv = 512.0f / sum;   // x512 keeps P out of fp16 subnormals

    uint4* o4 = (uint4*)(Ph + (size_t)row * MKV);
    #pragma unroll
    for (int i = 0; i < 4; i++) {
        uint32_t w[4];
        #pragma unroll
        for (int j = 0; j < 4; j++) {
            __half2 h = __halves2half2(__float2half_rn(v[i*8 + j*2]     * inv),
                                       __float2half_rn(v[i*8 + j*2 + 1] * inv));
            w[j] = *(uint32_t*)&h;
        }
        o4[tid + i * 256] = make_uint4(w[0], w[1], w[2], w[3]);
    }
}

// ---------------------------------------------------------------------------
extern "C" void kernel_launch(void* const* d_in, const int* in_sizes, int n_in,
                              void* d_out, int out_size)
{
    const float* x   = (const float*)d_in[0];
    const float* ctx = (const float*)d_in[1];
    const float* Wq  = (const float*)d_in[2];
    const float* bq  = (const float*)d_in[3];
    const float* Wk  = (const float*)d_in[4];
    const float* bk  = (const float*)d_in[5];
    const float* Wv  = (const float*)d_in[6];
    const float* bv  = (const float*)d_in[7];
    float* out = (float*)d_out;

    __half *xh,*ch,*wqh,*wkh,*wvh,*qh,*kh,*vh,*ph,*sp;
    cudaGetSymbolAddress((void**)&xh, g_xh);
    cudaGetSymbolAddress((void**)&ch, g_ch);
    cudaGetSymbolAddress((void**)&wqh, g_wqh);
    cudaGetSymbolAddress((void**)&wkh, g_wkh);
    cudaGetSymbolAddress((void**)&wvh, g_wvh);
    cudaGetSymbolAddress((void**)&qh, g_qh);
    cudaGetSymbolAddress((void**)&kh, g_kh);
    cudaGetSymbolAddress((void**)&vh, g_vh);
    cudaGetSymbolAddress((void**)&ph, g_ph);
    cudaGetSymbolAddress((void**)&sp, g_s);

    cudaFuncSetAttribute(hgemm<false, 1>, cudaFuncAttributeMaxDynamicSharedMemorySize, SMEM_TOTAL);
    cudaFuncSetAttribute(hgemm<true,  2>, cudaFuncAttributeMaxDynamicSharedMemorySize, SMEM_TOTAL);
    cudaFuncSetAttribute(hgemm<false, 0>, cudaFuncAttributeMaxDynamicSharedMemorySize, SMEM_TOTAL);

    // 1) convert fp32 inputs to fp16
    tohalf<<<(NQ  * DIMC / 4) / 256, 256>>>(x,   xh, NQ  * DIMC / 4);
    tohalf<<<(MKV * DIMC / 4) / 256, 256>>>(ctx, ch, MKV * DIMC / 4);
    tohalf<<<(DIMC * DIMC / 4) / 256, 256>>>(Wq, wqh, DIMC * DIMC / 4);
    tohalf<<<(DIMC * DIMC / 4) / 256, 256>>>(Wk, wkh, DIMC * DIMC / 4);
    tohalf<<<(DIMC * DIMC / 4) / 256, 256>>>(Wv, wvh, DIMC * DIMC / 4);

    // 2) projections (NN): out = fp16(x@W + b)
    hgemm<false, 1><<<dim3(DIMC/BN, NQ/BM),  256, SMEM_TOTAL>>>(
        xh, wqh, DIMC, DIMC, DIMC, bq, 1.0f, nullptr, qh, DIMC);
    hgemm<false, 1><<<dim3(DIMC/BN, MKV/BM), 256, SMEM_TOTAL>>>(
        ch, wkh, DIMC, DIMC, DIMC, bk, 1.0f, nullptr, kh, DIMC);
    hgemm<false, 1><<<dim3(DIMC/BN, MKV/BM), 256, SMEM_TOTAL>>>(
        ch, wvh, DIMC, DIMC, DIMC, bv, 1.0f, nullptr, vh, DIMC);

    // 3) scores S = fp16((q @ k^T) / 32)  (NT)
    hgemm<true, 2><<<dim3(MKV/BN, NQ/BM), 256, SMEM_TOTAL>>>(
        qh, kh, DIMC, DIMC, DIMC, nullptr, 1.0f / 32.0f, nullptr, sp, MKV);

    // 4) softmax rows (fp16 in) -> fp16 P (scaled x512)
    softmax_h<<<NQ, 256>>>(sp, ph);

    // 5) O = (P_512 @ v) / 512 (NN), fp32 out
    hgemm<false, 0><<<dim3(DIMC/BN, NQ/BM), 256, SMEM_TOTAL>>>(
        ph, vh, MKV, DIMC, MKV, nullptr, 1.0f / 512.0f, out, nullptr, DIMC);
}